// round 14
// baseline (speedup 1.0000x reference)
#include <cuda_runtime.h>
#include <cuda_fp16.h>
#include <cstdint>

// Problem constants
#define BATCH  2048
#define NITEMS 20000
#define KPAD   20096   // NITEMS padded to 2 x 10048 (157 x 64 per K-split)
#define KHALF  10048
#define EMB    512
#define HID    1024    // 2*D

// ---------------------------------------------------------------------------
// Scratch (no allocations -> __device__ globals)
// ---------------------------------------------------------------------------
__device__ __half g_noisyh[(size_t)BATCH * KPAD];    // masked likes fp16, padded
__device__ __half g_W1c[(size_t)KPAD * HID];         // enc_w1 fp16 [20096][1024]
__device__ __half g_W2c[(size_t)HID * EMB];          // enc_w2 fp16 [1024][512]
__device__ __half g_Wlr[(size_t)EMB * (2 * HID)];    // [512][2048] = lk_w1 ++ rc_w1
__device__ __half g_W4c[(size_t)HID * NITEMS];       // lk_w2 fp16 [1024][20000]
__device__ __half g_W6c[(size_t)HID * NITEMS];       // rc_w2 fp16 [1024][20000]
__device__ float  g_blr[2 * HID];                    // lk_b1 ++ rc_b1
__device__ float  g_psum[2 * (size_t)BATCH * HID];   // split-K partials (f32)
__device__ __half g_Hh[(size_t)BATCH * HID];         // encoder hidden fp16
__device__ __half g_Hh2[(size_t)BATCH * 2 * HID];    // fused head hiddens fp16
__device__ float  g_E[(size_t)BATCH * EMB];          // embed f32
__device__ __half g_Eh[(size_t)BATCH * EMB];         // embed fp16
__device__ __half g_Nrmh[(size_t)BATCH * EMB];       // normalized fp16
__device__ float  g_part[16 * NITEMS];
__device__ int    g_mask_mode;  // 0=u8, 1=i32, 2=f32

// ---------------------------------------------------------------------------
// PTX helpers (arch-generic sm_80-era instructions)
// ---------------------------------------------------------------------------
__device__ __forceinline__ uint32_t smem_u32(const void* p) {
    uint32_t a;
    asm("{ .reg .u64 t; cvta.to.shared.u64 t, %1; cvt.u32.u64 %0, t; }"
        : "=r"(a) : "l"(p));
    return a;
}
__device__ __forceinline__ void cp16(uint32_t dst, const void* src, int sz) {
    asm volatile("cp.async.cg.shared.global [%0], [%1], 16, %2;"
        :: "r"(dst), "l"(src), "r"(sz));
}
#define CP_COMMIT() asm volatile("cp.async.commit_group;" ::: "memory")
#define CP_WAIT(n)  asm volatile("cp.async.wait_group %0;" :: "n"(n) : "memory")

#define LDSM_X4(r, addr) \
    asm volatile("ldmatrix.sync.aligned.m8n8.x4.shared.b16 {%0,%1,%2,%3}, [%4];" \
        : "=r"((r)[0]), "=r"((r)[1]), "=r"((r)[2]), "=r"((r)[3]) : "r"(addr))

#define LDSM_X4_T(r, addr) \
    asm volatile("ldmatrix.sync.aligned.m8n8.x4.trans.shared.b16 {%0,%1,%2,%3}, [%4];" \
        : "=r"((r)[0]), "=r"((r)[1]), "=r"((r)[2]), "=r"((r)[3]) : "r"(addr))

__device__ __forceinline__ void mma16816(float* d, const uint32_t* a,
                                         uint32_t b0, uint32_t b1) {
    asm volatile(
        "mma.sync.aligned.m16n8k16.row.col.f32.f16.f16.f32 "
        "{%0,%1,%2,%3}, {%4,%5,%6,%7}, {%8,%9}, {%0,%1,%2,%3};"
        : "+f"(d[0]), "+f"(d[1]), "+f"(d[2]), "+f"(d[3])
        : "r"(a[0]), "r"(a[1]), "r"(a[2]), "r"(a[3]), "r"(b0), "r"(b1));
}

enum { ACT_RELU = 0, ACT_SIG = 1, ACT_NEG = 2, ACT_NONE = 3 };
// CTA tile 128 x 64, BK=64, 8 warps of 32x32, 3 stages, 3 CTAs/SM (24 warps).
#define BK 64
#define NSTAGE 3
#define BNT 64                    // CTA N-tile
#define ASZ 16384                 // A: 128 rows * 128B
#define BSZ 8192                  // B: 64 rows * 128B
#define SSZ (ASZ + BSZ)           // 24KB per stage -> 72KB total
#define GOCC 3

// ---------------------------------------------------------------------------
// GEMM body. Single __syncthreads per K-chunk: 3 smem stages, prefetch
// distance 2 (stage written at iter i is (i+2)%3, last read at i-1).
// ---------------------------------------------------------------------------
template<int ACT, bool HAS_BIAS, bool OUT_HALF, bool TRANSB>
__device__ __forceinline__ void gemm_body(
    const __half* __restrict__ A, const __half* __restrict__ Bt,
    const float* __restrict__ bias, void* __restrict__ Cout,
    int M, int N, int K, int lda, int ldb, int bx, int by, char* smem) {
    const uint32_t sbase = smem_u32(smem);

    const int tid = threadIdx.x;
    const int lane = tid & 31, wid = tid >> 5;
    const int wm = (wid & 3) * 32;        // warp m offset (4 m-warps)
    const int wn = (wid >> 2) * 32;       // warp n offset (2 n-warps)
    const int m0 = bx * 128;
    const int n0 = by * BNT;
    const int nch = K / BK;

    float acc[2][4][4];
    #pragma unroll
    for (int i = 0; i < 2; i++)
        #pragma unroll
        for (int j = 0; j < 4; j++)
            #pragma unroll
            for (int q = 0; q < 4; q++) acc[i][j][q] = 0.f;

    // ---- stage loader ----
    auto load_stage = [&](int ch, int st) {
        const int k0 = ch * BK;
        const uint32_t sA = sbase + st * SSZ;
        const uint32_t sB = sA + ASZ;
        #pragma unroll
        for (int u = 0; u < 4; u++) {
            int idx = tid + u * 256;
            int r = idx >> 3, c = idx & 7;
            const __half* src = A + (size_t)(m0 + r) * lda + k0 + c * 8;
            cp16(sA + r * 128 + ((c ^ (r & 7)) << 4), src, 16);
        }
        if constexpr (!TRANSB) {
            // B [N][K] K-major: 64 n-rows x 64 k = 8KB, 128B rows
            #pragma unroll
            for (int u = 0; u < 2; u++) {
                int idx = tid + u * 256;
                int r = idx >> 3, c = idx & 7;
                int n = n0 + r;
                const __half* src = Bt + (size_t)n * ldb + k0 + c * 8;
                cp16(sB + r * 128 + ((c ^ (r & 7)) << 4), src, (n < N) ? 16 : 0);
            }
        } else {
            // B [K][N] row-major: 64 k-rows x 64 n = 8KB, 128B rows
            #pragma unroll
            for (int u = 0; u < 2; u++) {
                int idx = tid + u * 256;
                int k = idx >> 3, c = idx & 7;
                const __half* src = Bt + (size_t)(k0 + k) * ldb + n0 + c * 8;
                uint32_t dst = sB + k * 128 + ((c ^ (k & 7)) << 4);
                cp16(dst, src, (n0 + c * 8 + 8 <= N) ? 16 : 0);
            }
        }
        CP_COMMIT();
    };

    // ldmatrix lane addressing
    const int aRow = wm + (lane & 15);
    const int aKsel = lane >> 4;
    const int swz = lane & 7;
    // non-trans B
    const int bRow = wn + ((lane >> 4) << 3) + (lane & 7);
    const int bKsel = (lane >> 3) & 1;
    // trans B: lane -> k row within k16, plus two n-octet byte offsets
    const int kLane = ((lane >> 3) & 1) * 8 + (lane & 7);
    int bOffT0 = 0, bOffT1 = 0;
    {
        int n0l = wn + ((lane >> 4) << 3);
        int c0 = n0l >> 3, c1 = (n0l + 16) >> 3;
        bOffT0 = ((c0 ^ (lane & 7)) << 4);
        bOffT1 = ((c1 ^ (lane & 7)) << 4);
    }

    // prologue: distance-2 prefetch
    load_stage(0, 0);
    load_stage(1, 1);

    for (int i = 0; i < nch; i++) {
        CP_WAIT(1);                  // stage i resident (<=1 group pending)
        __syncthreads();             // all warps done with stage (i-1) reads
        const int j = i + 2;
        if (j < nch) load_stage(j, j % NSTAGE);
        else         CP_COMMIT();    // keep group accounting aligned

        const uint32_t sA = sbase + (i % NSTAGE) * SSZ;
        const uint32_t sB = sA + ASZ;
        #pragma unroll
        for (int kk = 0; kk < 4; kk++) {
            uint32_t a[2][4], b[2][4];
            const uint32_t aByte = ((2 * kk + aKsel) ^ swz) << 4;
            #pragma unroll
            for (int mf = 0; mf < 2; mf++)
                LDSM_X4(a[mf], sA + (aRow + 16 * mf) * 128 + aByte);
            if constexpr (!TRANSB) {
                const uint32_t bByte = ((2 * kk + bKsel) ^ swz) << 4;
                #pragma unroll
                for (int nf2 = 0; nf2 < 2; nf2++)
                    LDSM_X4(b[nf2], sB + (bRow + 16 * nf2) * 128 + bByte);
            } else {
                const uint32_t rowB = sB + (kk * 16 + kLane) * 128;
                LDSM_X4_T(b[0], rowB + bOffT0);
                LDSM_X4_T(b[1], rowB + bOffT1);
            }
            #pragma unroll
            for (int mf = 0; mf < 2; mf++)
                #pragma unroll
                for (int nf = 0; nf < 4; nf++)
                    mma16816(acc[mf][nf], a[mf],
                             b[nf >> 1][(nf & 1) * 2],
                             b[nf >> 1][(nf & 1) * 2 + 1]);
        }
    }

    // ---- epilogue ----
    #pragma unroll
    for (int mf = 0; mf < 2; mf++) {
        const int row = m0 + wm + mf * 16 + (lane >> 2);
        #pragma unroll
        for (int nf = 0; nf < 4; nf++) {
            const int col = n0 + wn + nf * 8 + 2 * (lane & 3);
            if (col >= N) continue;
            float2 lo = make_float2(acc[mf][nf][0], acc[mf][nf][1]);
            float2 hi = make_float2(acc[mf][nf][2], acc[mf][nf][3]);
            if (HAS_BIAS) {
                float2 bb = *reinterpret_cast<const float2*>(bias + col);
                lo.x += bb.x; lo.y += bb.y;
                hi.x += bb.x; hi.y += bb.y;
            }
            if (ACT == ACT_RELU) {
                lo.x = fmaxf(lo.x, 0.f); lo.y = fmaxf(lo.y, 0.f);
                hi.x = fmaxf(hi.x, 0.f); hi.y = fmaxf(hi.y, 0.f);
            } else if (ACT == ACT_SIG) {
                lo.x = __fdividef(1.f, 1.f + __expf(-lo.x));
                lo.y = __fdividef(1.f, 1.f + __expf(-lo.y));
                hi.x = __fdividef(1.f, 1.f + __expf(-hi.x));
                hi.y = __fdividef(1.f, 1.f + __expf(-hi.y));
            } else if (ACT == ACT_NEG) {
                lo.x = -lo.x; lo.y = -lo.y;
                hi.x = -hi.x; hi.y = -hi.y;
            }  // ACT_NONE: raw
            if (OUT_HALF) {
                __half* C = (__half*)Cout;
                *reinterpret_cast<__half2*>(C + (size_t)row * N + col) =
                    __floats2half2_rn(lo.x, lo.y);
                *reinterpret_cast<__half2*>(C + (size_t)(row + 8) * N + col) =
                    __floats2half2_rn(hi.x, hi.y);
            } else {
                float* C = (float*)Cout;
                *reinterpret_cast<float2*>(C + (size_t)row * N + col) = lo;
                *reinterpret_cast<float2*>(C + (size_t)(row + 8) * N + col) = hi;
            }
        }
    }
}

// ---------------------------------------------------------------------------
// Standalone GEMM kernel (with dual-pointer wave-merge mode)
// ---------------------------------------------------------------------------
template<int ACT, bool HAS_BIAS, bool OUT_HALF, bool TRANSB>
__global__ __launch_bounds__(256, GOCC)
void hmma_gemm(const __half* __restrict__ Ap, const __half* __restrict__ Bp,
               const float* __restrict__ biasp, void* __restrict__ Coutp,
               int M, int N, int K, int lda, int ldb,
               const __half* A2, const __half* B2,
               const float* bias2, void* Cout2, int nSplit) {
    extern __shared__ __align__(128) char smem[];
    const __half* A   = Ap;
    const __half* Bt  = Bp;
    const float* bias = biasp;
    void* Cout        = Coutp;
    int by = blockIdx.y;
    if (by >= nSplit) {
        by -= nSplit;
        A = A2; Bt = B2; bias = bias2; Cout = Cout2;
    }
    gemm_body<ACT, HAS_BIAS, OUT_HALF, TRANSB>(
        A, Bt, bias, Cout, M, N, K, lda, ldb, blockIdx.x, by, smem);
}

// ---------------------------------------------------------------------------
// Merged sim + head-hidden kernel. sim: 16x32=512 CTAs; hid: 16x32=512.
// ---------------------------------------------------------------------------
__global__ __launch_bounds__(256, GOCC)
void simhid_kernel(const __half* __restrict__ Nrmh, float* __restrict__ out_sim,
                   const __half* __restrict__ Eh, const __half* __restrict__ Wlr,
                   const float* __restrict__ blr, __half* __restrict__ Hh2) {
    extern __shared__ __align__(128) char smem[];
    int bid = blockIdx.x;
    if (bid < 512) {
        gemm_body<ACT_NEG, false, false, false>(
            Nrmh, Nrmh, nullptr, out_sim, BATCH, BATCH, EMB, EMB, EMB,
            bid & 15, bid >> 4, smem);
    } else {
        bid -= 512;
        gemm_body<ACT_RELU, true, true, true>(
            Eh, Wlr, blr, Hh2, BATCH, 2 * HID, EMB, EMB, 2 * HID,
            bid & 15, bid >> 4, smem);
    }
}

// ---------------------------------------------------------------------------
// Aux device helpers (block-indexed bodies of the prep kernels)
// ---------------------------------------------------------------------------
__device__ __forceinline__ void aux_popular_reduce(
    int b, const float* __restrict__ part, float* __restrict__ out_pop) {
    int i = b * 256 + threadIdx.x;
    if (i >= NITEMS) return;
    float s = 0.f;
    #pragma unroll
    for (int c = 0; c < 16; c++) s += part[c * NITEMS + i];
    out_pop[i] = s * (1.0f / (float)BATCH);
}

__device__ __forceinline__ void aux_convert_pad(
    int b, const float* __restrict__ in, __half* __restrict__ out,
    long validElems, long total8) {
    long i = (long)b * 256 + threadIdx.x;
    if (i >= total8) return;
    long e = i * 8;
    __half2 h[4];
    if (e + 8 <= validElems) {
        float4 a = *reinterpret_cast<const float4*>(in + e);
        float4 bb = *reinterpret_cast<const float4*>(in + e + 4);
        h[0] = __floats2half2_rn(a.x, a.y);
        h[1] = __floats2half2_rn(a.z, a.w);
        h[2] = __floats2half2_rn(bb.x, bb.y);
        h[3] = __floats2half2_rn(bb.z, bb.w);
    } else {
        h[0] = h[1] = h[2] = h[3] = __floats2half2_rn(0.f, 0.f);
    }
    __half2* dst = reinterpret_cast<__half2*>(out + e);
    dst[0] = h[0]; dst[1] = h[1]; dst[2] = h[2]; dst[3] = h[3];
}

__device__ __forceinline__ void aux_convert_cols(
    int b, const float* __restrict__ in, __half* __restrict__ out,
    int C, int ldo, int colOff, int total8) {
    int i = b * 256 + threadIdx.x;
    if (i >= total8) return;
    long e = (long)i * 8;
    int k = (int)(e / C);
    int c = (int)(e - (long)k * C);
    float4 a = *reinterpret_cast<const float4*>(in + e);
    float4 bb = *reinterpret_cast<const float4*>(in + e + 4);
    __half2* dst = reinterpret_cast<__half2*>(out + (size_t)k * ldo + colOff + c);
    dst[0] = __floats2half2_rn(a.x, a.y);
    dst[1] = __floats2half2_rn(a.z, a.w);
    dst[2] = __floats2half2_rn(bb.x, bb.y);
    dst[3] = __floats2half2_rn(bb.z, bb.w);
}

__device__ __forceinline__ void aux_concat2(
    int b, const float* __restrict__ a, const float* __restrict__ bsrc,
    float* __restrict__ o, int n) {
    int i = b * 256 + threadIdx.x;
    if (i < n) o[i] = a[i];
    else if (i < 2 * n) o[i] = bsrc[i - n];
}

// ---------------------------------------------------------------------------
// MEGA kernel: split-K gemm1 (512 CTAs: 16x16 tiles x 2 K-splits) + prep aux
// ---------------------------------------------------------------------------
#define MEGA_GEMM 512
#define AUX_RED   79
#define AUX_W2    256
#define AUX_WLR1  256
#define AUX_WLR2  256
#define AUX_BLR   8
#define AUX_W4    10000
#define AUX_W6    10000
#define MEGA_BLOCKS (MEGA_GEMM + AUX_RED + AUX_W2 + AUX_WLR1 + AUX_WLR2 + \
                     AUX_BLR + AUX_W4 + AUX_W6)

__global__ __launch_bounds__(256, GOCC)
void mega_kernel(const __half* __restrict__ noisyh,
                 const __half* __restrict__ W1c, float* __restrict__ psum,
                 const float* __restrict__ part, float* __restrict__ out_pop,
                 const float* __restrict__ enc_w2, __half* __restrict__ W2c,
                 const float* __restrict__ lk_w1, const float* __restrict__ rc_w1,
                 __half* __restrict__ Wlr,
                 const float* __restrict__ lk_b1, const float* __restrict__ rc_b1,
                 float* __restrict__ blr,
                 const float* __restrict__ lk_w2, __half* __restrict__ W4c,
                 const float* __restrict__ rc_w2, __half* __restrict__ W6c) {
    extern __shared__ __align__(128) char smem[];
    int bid = blockIdx.x;
    if (bid < MEGA_GEMM) {
        int z = bid >> 8;            // K split 0/1
        int r = bid & 255;
        int bx = r & 15;             // m tile (16)
        int by = r >> 4;             // n tile (16 = HID/64)
        const __half* A = noisyh + (size_t)z * KHALF;
        const __half* B = W1c + (size_t)z * KHALF * HID;
        float* C = psum + (size_t)z * BATCH * HID;
        gemm_body<ACT_NONE, false, false, true>(
            A, B, nullptr, C, BATCH, HID, KHALF, KPAD, HID, bx, by, smem);
        return;
    }
    int aux = bid - MEGA_GEMM;
    if (aux < AUX_RED) { aux_popular_reduce(aux, part, out_pop); return; }
    aux -= AUX_RED;
    if (aux < AUX_W2) {
        aux_convert_pad(aux, enc_w2, W2c, (long)HID * EMB, (long)HID * EMB / 8);
        return;
    }
    aux -= AUX_W2;
    if (aux < AUX_WLR1) {
        aux_convert_cols(aux, lk_w1, Wlr, HID, 2 * HID, 0, EMB * HID / 8);
        return;
    }
    aux -= AUX_WLR1;
    if (aux < AUX_WLR2) {
        aux_convert_cols(aux, rc_w1, Wlr, HID, 2 * HID, HID, EMB * HID / 8);
        return;
    }
    aux -= AUX_WLR2;
    if (aux < AUX_BLR) { aux_concat2(aux, lk_b1, rc_b1, blr, HID); return; }
    aux -= AUX_BLR;
    if (aux < AUX_W4) {
        aux_convert_pad(aux, lk_w2, W4c, (long)HID * NITEMS,
                        (long)HID * NITEMS / 8);
        return;
    }
    aux -= AUX_W4;
    aux_convert_pad(aux, rc_w2, W6c, (long)HID * NITEMS,
                    (long)HID * NITEMS / 8);
}

// ---------------------------------------------------------------------------
// Small kernels
// ---------------------------------------------------------------------------
__global__ void probe_mask_kernel(const unsigned int* __restrict__ w) {
    __shared__ int s_other, s_f1, s_i1;
    if (threadIdx.x == 0) { s_other = 0; s_f1 = 0; s_i1 = 0; }
    __syncthreads();
    int lo = 0, lf = 0, li = 0;
    for (int i = threadIdx.x; i < 65536; i += blockDim.x) {
        unsigned v = w[i];
        if (v == 0u) continue;
        else if (v == 1u) li++;
        else if (v == 0x3F800000u) lf++;
        else lo++;
    }
    atomicAdd(&s_other, lo); atomicAdd(&s_f1, lf); atomicAdd(&s_i1, li);
    __syncthreads();
    if (threadIdx.x == 0) {
        int mode;
        if (s_other > 1024) mode = 0;
        else if (s_f1 >= s_i1) mode = 2;
        else mode = 1;
        g_mask_mode = mode;
    }
}

// Merged prep: premask+popular partials + W1 convert
#define PREM_X 79                       // ceil(KPAD/256)
#define PREM_BLOCKS (PREM_X * 16)       // 1264
#define W1_BLOCKS ((KPAD * HID / 8) / 256)  // 10048
#define PREP_BLOCKS (PREM_BLOCKS + W1_BLOCKS)

__global__ void prep_kernel(const float* __restrict__ likes,
                            const void* __restrict__ mask,
                            __half* __restrict__ noisy,
                            float* __restrict__ part,
                            const float* __restrict__ enc_w1,
                            __half* __restrict__ W1c) {
    int bid = blockIdx.x;
    if (bid >= PREM_BLOCKS) {
        aux_convert_pad(bid - PREM_BLOCKS, enc_w1, W1c,
                        (long)NITEMS * HID, (long)KPAD * HID / 8);
        return;
    }
    const int mode = g_mask_mode;
    const int col = (bid % PREM_X) * 256 + threadIdx.x;
    if (col >= KPAD) return;
    const int r0 = (bid / PREM_X) * 128;

    if (col >= NITEMS) {  // padding region: zero noisy, no popular
        const __half hz = __float2half_rn(0.f);
        for (int r = 0; r < 128; r++)
            noisy[(size_t)(r0 + r) * KPAD + col] = hz;
        return;
    }

    const unsigned char* m8 = (const unsigned char*)mask;
    const int*           mi = (const int*)mask;
    const float*         mf = (const float*)mask;

    float sum = 0.f;
    #pragma unroll 4
    for (int r = 0; r < 128; r++) {
        size_t e = (size_t)(r0 + r) * NITEMS + col;
        float v = likes[e];
        sum += v;
        bool drop;
        if (mode == 0)      drop = (m8[e] != 0);
        else if (mode == 1) drop = (mi[e] != 0);
        else                drop = (mf[e] != 0.f);
        noisy[(size_t)(r0 + r) * KPAD + col] = __float2half_rn(drop ? 0.f : v);
    }
    part[(bid / PREM_X) * NITEMS + col] = sum;
}

// combine split-K partials: Hh = fp16(relu(p0 + p1 + bias))
__global__ void combine_splitk_kernel(const float* __restrict__ p,
                                      const float* __restrict__ bias,
                                      __half* __restrict__ out) {
    const size_t MN = (size_t)BATCH * HID;
    size_t e = ((size_t)blockIdx.x * 256 + threadIdx.x) * 4;
    if (e >= MN) return;
    int col = (int)(e & (HID - 1));
    float4 a = *reinterpret_cast<const float4*>(p + e);
    float4 b = *reinterpret_cast<const float4*>(p + MN + e);
    float4 bb = *reinterpret_cast<const float4*>(bias + col);
    float x0 = fmaxf(a.x + b.x + bb.x, 0.f);
    float x1 = fmaxf(a.y + b.y + bb.y, 0.f);
    float x2 = fmaxf(a.z + b.z + bb.z, 0.f);
    float x3 = fmaxf(a.w + b.w + bb.w, 0.f);
    __half2* dst = reinterpret_cast<__half2*>(out + e);
    dst[0] = __floats2half2_rn(x0, x1);
    dst[1] = __floats2half2_rn(x2, x3);
}

// per-row l2 normalize; emit fp16 normalized AND fp16 copy of E
__global__ void norm_half_kernel(const float* __restrict__ E,
                                 __half* __restrict__ Nrmh,
                                 __half* __restrict__ Eh) {
    int row = blockIdx.x;
    int t = threadIdx.x;
    float4 v = reinterpret_cast<const float4*>(E + (size_t)row * EMB)[t];
    float ss = v.x * v.x + v.y * v.y + v.z * v.z + v.w * v.w;
    #pragma unroll
    for (int o = 16; o > 0; o >>= 1)
        ss += __shfl_xor_sync(0xFFFFFFFFu, ss, o);
    __shared__ float ws[4];
    if ((t & 31) == 0) ws[t >> 5] = ss;
    __syncthreads();
    float tot = ws[0] + ws[1] + ws[2] + ws[3];
    float inv = rsqrtf(fmaxf(tot, 1e-12f));
    __half2* eh = reinterpret_cast<__half2*>(Eh + (size_t)row * EMB + t * 4);
    eh[0] = __floats2half2_rn(v.x, v.y);
    eh[1] = __floats2half2_rn(v.z, v.w);
    __half2* nh = reinterpret_cast<__half2*>(Nrmh + (size_t)row * EMB + t * 4);
    nh[0] = __floats2half2_rn(v.x * inv, v.y * inv);
    nh[1] = __floats2half2_rn(v.z * inv, v.w * inv);
}

#define NO_DUAL nullptr, nullptr, nullptr, nullptr, 0x40000000

// ---------------------------------------------------------------------------
// Launch
// ---------------------------------------------------------------------------
extern "C" void kernel_launch(void* const* d_in, const int* in_sizes, int n_in,
                              void* d_out, int out_size) {
    const float* likes  = (const float*)d_in[1];
    const void*  nmask  = d_in[2];
    const float* enc_w1 = (const float*)d_in[3];
    const float* enc_b1 = (const float*)d_in[4];
    const float* enc_w2 = (const float*)d_in[5];
    const float* enc_b2 = (const float*)d_in[6];
    const float* lk_w1  = (const float*)d_in[7];
    const float* lk_b1  = (const float*)d_in[8];
    const float* lk_w2  = (const float*)d_in[9];
    const float* lk_b2  = (const float*)d_in[10];
    const float* rc_w1  = (const float*)d_in[11];
    const float* rc_b1  = (const float*)d_in[12];
    const float* rc_w2  = (const float*)d_in[13];
    const float* rc_b2  = (const float*)d_in[14];

    float* out       = (float*)d_out;
    float* out_likes = out;
    float* out_sim   = out_likes + (size_t)BATCH * NITEMS;
    float* out_rec   = out_sim + (size_t)BATCH * BATCH;
    float* out_pop   = out_rec + (size_t)BATCH * NITEMS;

    __half *noisyh, *W1c, *W2c, *Wlr, *W4c, *W6c, *Hh, *Hh2, *Eh, *Nrmh;
    float *E, *part, *blr, *psum;
    cudaGetSymbolAddress((void**)&noisyh, g_noisyh);
    cudaGetSymbolAddress((void**)&W1c, g_W1c);
    cudaGetSymbolAddress((void**)&W2c, g_W2c);
    cudaGetSymbolAddress((void**)&Wlr, g_Wlr);
    cudaGetSymbolAddress((void**)&W4c, g_W4c);
    cudaGetSymbolAddress((void**)&W6c, g_W6c);
    cudaGetSymbolAddress((void**)&blr, g_blr);
    cudaGetSymbolAddress((void**)&psum, g_psum);
    cudaGetSymbolAddress((void**)&Hh, g_Hh);
    cudaGetSymbolAddress((void**)&Hh2, g_Hh2);
    cudaGetSymbolAddress((void**)&E, g_E);
    cudaGetSymbolAddress((void**)&Eh, g_Eh);
    cudaGetSymbolAddress((void**)&Nrmh, g_Nrmh);
    cudaGetSymbolAddress((void**)&part, g_part);

    const int smem = NSTAGE * SSZ;  // 72KB -> 3 CTAs/SM
    cudaFuncSetAttribute(mega_kernel,
                         cudaFuncAttributeMaxDynamicSharedMemorySize, smem);
    cudaFuncSetAttribute(simhid_kernel,
                         cudaFuncAttributeMaxDynamicSharedMemorySize, smem);
    cudaFuncSetAttribute(hmma_gemm<ACT_RELU, true, false, true>,
                         cudaFuncAttributeMaxDynamicSharedMemorySize, smem);
    cudaFuncSetAttribute(hmma_gemm<ACT_SIG, true, false, true>,
                         cudaFuncAttributeMaxDynamicSharedMemorySize, smem);

    // 1: mask probe
    probe_mask_kernel<<<1, 256>>>((const unsigned int*)nmask);
    // 2: merged prep -- denoise+popular partials + enc_w1 convert
    prep_kernel<<<PREP_BLOCKS, 256>>>(likes, nmask, noisyh, part, enc_w1, W1c);
    // 3: MEGA -- split-K gemm1 + all remaining independent prep work
    mega_kernel<<<MEGA_BLOCKS, 256, smem>>>(
        noisyh, W1c, psum, part, out_pop,
        enc_w2, W2c, lk_w1, rc_w1, Wlr, lk_b1, rc_b1, blr,
        lk_w2, W4c, rc_w2, W6c);
    // 4: combine partials -> Hh = fp16(relu(p0+p1+b1))
    combine_splitk_kernel<<<(int)(((size_t)BATCH * HID / 4 + 255) / 256), 256>>>(
        psum, enc_b1, Hh);

    // 5: encoder layer 2  (grid 16 x 8, N tiles of 64)
    hmma_gemm<ACT_RELU, true, false, true>
        <<<dim3(BATCH / 128, EMB / BNT), 256, smem>>>(
        Hh, W2c, enc_b2, E, BATCH, EMB, HID, HID, EMB, NO_DUAL);
    // 6: norm
    norm_half_kernel<<<BATCH, 128>>>(E, Nrmh, Eh);

    // 7: merged sim + head-hidden (1024 CTAs)
    simhid_kernel<<<1024, 256, smem>>>(Nrmh, out_sim, Eh, Wlr, blr, Hh2);

    // 8: BOTH head outputs in ONE launch (wave merge), N tiles of 64
    const int nTiles = (NITEMS + BNT - 1) / BNT;  // 313
    hmma_gemm<ACT_SIG, true, false, true>
        <<<dim3(BATCH / 128, 2 * nTiles), 256, smem>>>(
        Hh2, W4c, lk_b2, out_likes, BATCH, NITEMS, HID, 2 * HID, NITEMS,
        Hh2 + HID, W6c, rc_b2, out_rec, nTiles);
}

// round 15
// speedup vs baseline: 1.2136x; 1.2136x over previous
#include <cuda_runtime.h>
#include <cuda_fp16.h>
#include <cstdint>

// Problem constants
#define BATCH  2048
#define NITEMS 20000
#define KPAD   20096   // NITEMS padded to 2 x 10048 (157 x 64 per K-split)
#define KHALF  10048
#define EMB    512
#define HID    1024    // 2*D

// ---------------------------------------------------------------------------
// Scratch (no allocations -> __device__ globals)
// ---------------------------------------------------------------------------
__device__ __half g_noisyh[(size_t)BATCH * KPAD];    // masked likes fp16, padded
__device__ __half g_W1c[(size_t)KPAD * HID];         // enc_w1 fp16 [20096][1024]
__device__ __half g_W2c[(size_t)HID * EMB];          // enc_w2 fp16 [1024][512]
__device__ __half g_Wlr[(size_t)EMB * (2 * HID)];    // [512][2048] = lk_w1 ++ rc_w1
__device__ __half g_W4c[(size_t)HID * NITEMS];       // lk_w2 fp16 [1024][20000]
__device__ __half g_W6c[(size_t)HID * NITEMS];       // rc_w2 fp16 [1024][20000]
__device__ float  g_blr[2 * HID];                    // lk_b1 ++ rc_b1
__device__ float  g_psum[2 * (size_t)BATCH * HID];   // split-K partials (f32)
__device__ __half g_Hh[(size_t)BATCH * HID];         // encoder hidden fp16
__device__ __half g_Hh2[(size_t)BATCH * 2 * HID];    // fused head hiddens fp16
__device__ float  g_E[(size_t)BATCH * EMB];          // embed f32
__device__ __half g_Eh[(size_t)BATCH * EMB];         // embed fp16
__device__ __half g_Nrmh[(size_t)BATCH * EMB];       // normalized fp16
__device__ float  g_part[16 * NITEMS];

// ---------------------------------------------------------------------------
// PTX helpers (arch-generic sm_80-era instructions)
// ---------------------------------------------------------------------------
__device__ __forceinline__ uint32_t smem_u32(const void* p) {
    uint32_t a;
    asm("{ .reg .u64 t; cvta.to.shared.u64 t, %1; cvt.u32.u64 %0, t; }"
        : "=r"(a) : "l"(p));
    return a;
}
__device__ __forceinline__ void cp16(uint32_t dst, const void* src, int sz) {
    asm volatile("cp.async.cg.shared.global [%0], [%1], 16, %2;"
        :: "r"(dst), "l"(src), "r"(sz));
}
#define CP_COMMIT() asm volatile("cp.async.commit_group;" ::: "memory")
#define CP_WAIT(n)  asm volatile("cp.async.wait_group %0;" :: "n"(n) : "memory")

#define LDSM_X4(r, addr) \
    asm volatile("ldmatrix.sync.aligned.m8n8.x4.shared.b16 {%0,%1,%2,%3}, [%4];" \
        : "=r"((r)[0]), "=r"((r)[1]), "=r"((r)[2]), "=r"((r)[3]) : "r"(addr))

#define LDSM_X4_T(r, addr) \
    asm volatile("ldmatrix.sync.aligned.m8n8.x4.trans.shared.b16 {%0,%1,%2,%3}, [%4];" \
        : "=r"((r)[0]), "=r"((r)[1]), "=r"((r)[2]), "=r"((r)[3]) : "r"(addr))

__device__ __forceinline__ void mma16816(float* d, const uint32_t* a,
                                         uint32_t b0, uint32_t b1) {
    asm volatile(
        "mma.sync.aligned.m16n8k16.row.col.f32.f16.f16.f32 "
        "{%0,%1,%2,%3}, {%4,%5,%6,%7}, {%8,%9}, {%0,%1,%2,%3};"
        : "+f"(d[0]), "+f"(d[1]), "+f"(d[2]), "+f"(d[3])
        : "r"(a[0]), "r"(a[1]), "r"(a[2]), "r"(a[3]), "r"(b0), "r"(b1));
}

enum { ACT_RELU = 0, ACT_SIG = 1, ACT_NEG = 2, ACT_NONE = 3 };
#define BK 64
#define NSTAGE 3
#define ASZ 16384                 // A: 128 rows * 128B ; B(trans): 64 rows * 256B
#define SSZ 32768                 // A + B per stage (BN=128 body)

// ---------------------------------------------------------------------------
// GEMM body, CTA tile 128x128, 8 warps of 64x32, occ 2. (R13-proven)
// Single __syncthreads per K-chunk; 3 stages, prefetch distance 2.
// ---------------------------------------------------------------------------
template<int ACT, bool HAS_BIAS, bool OUT_HALF, bool TRANSB>
__device__ __forceinline__ void gemm_body(
    const __half* __restrict__ A, const __half* __restrict__ Bt,
    const float* __restrict__ bias, void* __restrict__ Cout,
    int M, int N, int K, int lda, int ldb, int bx, int by, char* smem) {
    const uint32_t sbase = smem_u32(smem);

    const int tid = threadIdx.x;
    const int lane = tid & 31, wid = tid >> 5;
    const int wm = (wid & 1) * 64;
    const int wn = (wid >> 1) * 32;
    const int m0 = bx * 128;
    const int n0 = by * 128;
    const int nch = K / BK;

    float acc[4][4][4];
    #pragma unroll
    for (int i = 0; i < 4; i++)
        #pragma unroll
        for (int j = 0; j < 4; j++)
            #pragma unroll
            for (int q = 0; q < 4; q++) acc[i][j][q] = 0.f;

    auto load_stage = [&](int ch, int st) {
        const int k0 = ch * BK;
        const uint32_t sA = sbase + st * SSZ;
        const uint32_t sB = sA + ASZ;
        #pragma unroll
        for (int u = 0; u < 4; u++) {
            int idx = tid + u * 256;
            int r = idx >> 3, c = idx & 7;
            const __half* src = A + (size_t)(m0 + r) * lda + k0 + c * 8;
            cp16(sA + r * 128 + ((c ^ (r & 7)) << 4), src, 16);
        }
        if constexpr (!TRANSB) {
            #pragma unroll
            for (int u = 0; u < 4; u++) {
                int idx = tid + u * 256;
                int r = idx >> 3, c = idx & 7;
                int n = n0 + r;
                const __half* src = Bt + (size_t)n * ldb + k0 + c * 8;
                cp16(sB + r * 128 + ((c ^ (r & 7)) << 4), src, (n < N) ? 16 : 0);
            }
        } else {
            // B tile [BK=64 k-rows][128 n], 256B per k-row, per-128B-half swizzle
            #pragma unroll
            for (int u = 0; u < 4; u++) {
                int idx = tid + u * 256;
                int k = idx >> 4, c = idx & 15;
                const __half* src = Bt + (size_t)(k0 + k) * ldb + n0 + c * 8;
                uint32_t dst = sB + k * 256 + ((c >> 3) << 7)
                             + (((c & 7) ^ (k & 7)) << 4);
                cp16(dst, src, (n0 + c * 8 + 8 <= N) ? 16 : 0);
            }
        }
        CP_COMMIT();
    };

    const int aRow = wm + (lane & 15);
    const int aKsel = lane >> 4;
    const int swz = lane & 7;
    const int bRow = wn + ((lane >> 4) << 3) + (lane & 7);
    const int bKsel = (lane >> 3) & 1;
    const int kLane = ((lane >> 3) & 1) * 8 + (lane & 7);
    int bOffT0 = 0, bOffT1 = 0;
    {
        int n0l = wn + ((lane >> 4) << 3);
        int c0 = n0l >> 3, c1 = (n0l + 16) >> 3;
        bOffT0 = ((c0 >> 3) << 7) + (((c0 & 7) ^ (lane & 7)) << 4);
        bOffT1 = ((c1 >> 3) << 7) + (((c1 & 7) ^ (lane & 7)) << 4);
    }

    load_stage(0, 0);
    load_stage(1, 1);

    for (int i = 0; i < nch; i++) {
        CP_WAIT(1);
        __syncthreads();
        const int j = i + 2;
        if (j < nch) load_stage(j, j % NSTAGE);
        else         CP_COMMIT();

        const uint32_t sA = sbase + (i % NSTAGE) * SSZ;
        const uint32_t sB = sA + ASZ;
        #pragma unroll
        for (int kk = 0; kk < 4; kk++) {
            uint32_t a[4][4], b[2][4];
            const uint32_t aByte = ((2 * kk + aKsel) ^ swz) << 4;
            #pragma unroll
            for (int mf = 0; mf < 4; mf++)
                LDSM_X4(a[mf], sA + (aRow + 16 * mf) * 128 + aByte);
            if constexpr (!TRANSB) {
                const uint32_t bByte = ((2 * kk + bKsel) ^ swz) << 4;
                #pragma unroll
                for (int nf2 = 0; nf2 < 2; nf2++)
                    LDSM_X4(b[nf2], sB + (bRow + 16 * nf2) * 128 + bByte);
            } else {
                const uint32_t rowB = sB + (kk * 16 + kLane) * 256;
                LDSM_X4_T(b[0], rowB + bOffT0);
                LDSM_X4_T(b[1], rowB + bOffT1);
            }
            #pragma unroll
            for (int mf = 0; mf < 4; mf++)
                #pragma unroll
                for (int nf = 0; nf < 4; nf++)
                    mma16816(acc[mf][nf], a[mf],
                             b[nf >> 1][(nf & 1) * 2],
                             b[nf >> 1][(nf & 1) * 2 + 1]);
        }
    }

    #pragma unroll
    for (int mf = 0; mf < 4; mf++) {
        const int row = m0 + wm + mf * 16 + (lane >> 2);
        #pragma unroll
        for (int nf = 0; nf < 4; nf++) {
            const int col = n0 + wn + nf * 8 + 2 * (lane & 3);
            if (col >= N) continue;
            float2 lo = make_float2(acc[mf][nf][0], acc[mf][nf][1]);
            float2 hi = make_float2(acc[mf][nf][2], acc[mf][nf][3]);
            if (HAS_BIAS) {
                float2 bb = *reinterpret_cast<const float2*>(bias + col);
                lo.x += bb.x; lo.y += bb.y;
                hi.x += bb.x; hi.y += bb.y;
            }
            if (ACT == ACT_RELU) {
                lo.x = fmaxf(lo.x, 0.f); lo.y = fmaxf(lo.y, 0.f);
                hi.x = fmaxf(hi.x, 0.f); hi.y = fmaxf(hi.y, 0.f);
            } else if (ACT == ACT_SIG) {
                lo.x = __fdividef(1.f, 1.f + __expf(-lo.x));
                lo.y = __fdividef(1.f, 1.f + __expf(-lo.y));
                hi.x = __fdividef(1.f, 1.f + __expf(-hi.x));
                hi.y = __fdividef(1.f, 1.f + __expf(-hi.y));
            } else if (ACT == ACT_NEG) {
                lo.x = -lo.x; lo.y = -lo.y;
                hi.x = -hi.x; hi.y = -hi.y;
            }
            if (OUT_HALF) {
                __half* C = (__half*)Cout;
                *reinterpret_cast<__half2*>(C + (size_t)row * N + col) =
                    __floats2half2_rn(lo.x, lo.y);
                *reinterpret_cast<__half2*>(C + (size_t)(row + 8) * N + col) =
                    __floats2half2_rn(hi.x, hi.y);
            } else {
                float* C = (float*)Cout;
                *reinterpret_cast<float2*>(C + (size_t)row * N + col) = lo;
                *reinterpret_cast<float2*>(C + (size_t)(row + 8) * N + col) = hi;
            }
        }
    }
}

// ---------------------------------------------------------------------------
// GEMM body, CTA tile 128x64, TRANSB only (R14-proven geometry). Used for the
// small encoder-layer-2 GEMM to double its CTA parallelism (64 -> 128 CTAs).
// ---------------------------------------------------------------------------
#define BSZ64 8192
#define SSZ64 (ASZ + BSZ64)

template<int ACT, bool HAS_BIAS, bool OUT_HALF>
__device__ __forceinline__ void gemm_body64(
    const __half* __restrict__ A, const __half* __restrict__ Bt,
    const float* __restrict__ bias, void* __restrict__ Cout,
    int M, int N, int K, int lda, int ldb, int bx, int by, char* smem) {
    const uint32_t sbase = smem_u32(smem);

    const int tid = threadIdx.x;
    const int lane = tid & 31, wid = tid >> 5;
    const int wm = (wid & 3) * 32;        // 4 m-warps
    const int wn = (wid >> 2) * 32;       // 2 n-warps
    const int m0 = bx * 128;
    const int n0 = by * 64;
    const int nch = K / BK;

    float acc[2][4][4];
    #pragma unroll
    for (int i = 0; i < 2; i++)
        #pragma unroll
        for (int j = 0; j < 4; j++)
            #pragma unroll
            for (int q = 0; q < 4; q++) acc[i][j][q] = 0.f;

    auto load_stage = [&](int ch, int st) {
        const int k0 = ch * BK;
        const uint32_t sA = sbase + st * SSZ64;
        const uint32_t sB = sA + ASZ;
        #pragma unroll
        for (int u = 0; u < 4; u++) {
            int idx = tid + u * 256;
            int r = idx >> 3, c = idx & 7;
            const __half* src = A + (size_t)(m0 + r) * lda + k0 + c * 8;
            cp16(sA + r * 128 + ((c ^ (r & 7)) << 4), src, 16);
        }
        // B [K][N] row-major: 64 k-rows x 64 n, 128B rows
        #pragma unroll
        for (int u = 0; u < 2; u++) {
            int idx = tid + u * 256;
            int k = idx >> 3, c = idx & 7;
            const __half* src = Bt + (size_t)(k0 + k) * ldb + n0 + c * 8;
            uint32_t dst = sB + k * 128 + ((c ^ (k & 7)) << 4);
            cp16(dst, src, (n0 + c * 8 + 8 <= N) ? 16 : 0);
        }
        CP_COMMIT();
    };

    const int aRow = wm + (lane & 15);
    const int aKsel = lane >> 4;
    const int swz = lane & 7;
    const int kLane = ((lane >> 3) & 1) * 8 + (lane & 7);
    int bOffT0 = 0, bOffT1 = 0;
    {
        int n0l = wn + ((lane >> 4) << 3);
        int c0 = n0l >> 3, c1 = (n0l + 16) >> 3;
        bOffT0 = ((c0 ^ (lane & 7)) << 4);
        bOffT1 = ((c1 ^ (lane & 7)) << 4);
    }

    load_stage(0, 0);
    load_stage(1, 1);

    for (int i = 0; i < nch; i++) {
        CP_WAIT(1);
        __syncthreads();
        const int j = i + 2;
        if (j < nch) load_stage(j, j % NSTAGE);
        else         CP_COMMIT();

        const uint32_t sA = sbase + (i % NSTAGE) * SSZ64;
        const uint32_t sB = sA + ASZ;
        #pragma unroll
        for (int kk = 0; kk < 4; kk++) {
            uint32_t a[2][4], b[2][4];
            const uint32_t aByte = ((2 * kk + aKsel) ^ swz) << 4;
            #pragma unroll
            for (int mf = 0; mf < 2; mf++)
                LDSM_X4(a[mf], sA + (aRow + 16 * mf) * 128 + aByte);
            const uint32_t rowB = sB + (kk * 16 + kLane) * 128;
            LDSM_X4_T(b[0], rowB + bOffT0);
            LDSM_X4_T(b[1], rowB + bOffT1);
            #pragma unroll
            for (int mf = 0; mf < 2; mf++)
                #pragma unroll
                for (int nf = 0; nf < 4; nf++)
                    mma16816(acc[mf][nf], a[mf],
                             b[nf >> 1][(nf & 1) * 2],
                             b[nf >> 1][(nf & 1) * 2 + 1]);
        }
    }

    #pragma unroll
    for (int mf = 0; mf < 2; mf++) {
        const int row = m0 + wm + mf * 16 + (lane >> 2);
        #pragma unroll
        for (int nf = 0; nf < 4; nf++) {
            const int col = n0 + wn + nf * 8 + 2 * (lane & 3);
            if (col >= N) continue;
            float2 lo = make_float2(acc[mf][nf][0], acc[mf][nf][1]);
            float2 hi = make_float2(acc[mf][nf][2], acc[mf][nf][3]);
            if (HAS_BIAS) {
                float2 bb = *reinterpret_cast<const float2*>(bias + col);
                lo.x += bb.x; lo.y += bb.y;
                hi.x += bb.x; hi.y += bb.y;
            }
            if (ACT == ACT_RELU) {
                lo.x = fmaxf(lo.x, 0.f); lo.y = fmaxf(lo.y, 0.f);
                hi.x = fmaxf(hi.x, 0.f); hi.y = fmaxf(hi.y, 0.f);
            }
            if (OUT_HALF) {
                __half* C = (__half*)Cout;
                *reinterpret_cast<__half2*>(C + (size_t)row * N + col) =
                    __floats2half2_rn(lo.x, lo.y);
                *reinterpret_cast<__half2*>(C + (size_t)(row + 8) * N + col) =
                    __floats2half2_rn(hi.x, hi.y);
            } else {
                float* C = (float*)Cout;
                *reinterpret_cast<float2*>(C + (size_t)row * N + col) = lo;
                *reinterpret_cast<float2*>(C + (size_t)(row + 8) * N + col) = hi;
            }
        }
    }
}

// ---------------------------------------------------------------------------
// Standalone GEMM kernels
// ---------------------------------------------------------------------------
template<int ACT, bool HAS_BIAS, bool OUT_HALF, bool TRANSB>
__global__ __launch_bounds__(256, 2)
void hmma_gemm(const __half* __restrict__ Ap, const __half* __restrict__ Bp,
               const float* __restrict__ biasp, void* __restrict__ Coutp,
               int M, int N, int K, int lda, int ldb,
               const __half* A2, const __half* B2,
               const float* bias2, void* Cout2, int nSplit) {
    extern __shared__ __align__(128) char smem[];
    const __half* A   = Ap;
    const __half* Bt  = Bp;
    const float* bias = biasp;
    void* Cout        = Coutp;
    int by = blockIdx.y;
    if (by >= nSplit) {
        by -= nSplit;
        A = A2; Bt = B2; bias = bias2; Cout = Cout2;
    }
    gemm_body<ACT, HAS_BIAS, OUT_HALF, TRANSB>(
        A, Bt, bias, Cout, M, N, K, lda, ldb, blockIdx.x, by, smem);
}

// encoder layer 2 with 128x64 tiles (128 CTAs instead of 64)
__global__ __launch_bounds__(256, 2)
void gemm2_kernel(const __half* __restrict__ Hh, const __half* __restrict__ W2c,
                  const float* __restrict__ enc_b2, float* __restrict__ E) {
    extern __shared__ __align__(128) char smem[];
    gemm_body64<ACT_RELU, true, false>(
        Hh, W2c, enc_b2, E, BATCH, EMB, HID, HID, EMB,
        blockIdx.x, blockIdx.y, smem);
}

// merged sim + head-hidden
__global__ __launch_bounds__(256, 2)
void simhid_kernel(const __half* __restrict__ Nrmh, float* __restrict__ out_sim,
                   const __half* __restrict__ Eh, const __half* __restrict__ Wlr,
                   const float* __restrict__ blr, __half* __restrict__ Hh2) {
    extern __shared__ __align__(128) char smem[];
    int bid = blockIdx.x;
    if (bid < 256) {
        gemm_body<ACT_NEG, false, false, false>(
            Nrmh, Nrmh, nullptr, out_sim, BATCH, BATCH, EMB, EMB, EMB,
            bid & 15, bid >> 4, smem);
    } else {
        bid -= 256;
        gemm_body<ACT_RELU, true, true, true>(
            Eh, Wlr, blr, Hh2, BATCH, 2 * HID, EMB, EMB, 2 * HID,
            bid & 15, bid >> 4, smem);
    }
}

// ---------------------------------------------------------------------------
// Aux device helpers
// ---------------------------------------------------------------------------
__device__ __forceinline__ void aux_popular_reduce(
    int b, const float* __restrict__ part, float* __restrict__ out_pop) {
    int i = b * 256 + threadIdx.x;
    if (i >= NITEMS) return;
    float s = 0.f;
    #pragma unroll
    for (int c = 0; c < 16; c++) s += part[c * NITEMS + i];
    out_pop[i] = s * (1.0f / (float)BATCH);
}

__device__ __forceinline__ void aux_convert_pad(
    int b, const float* __restrict__ in, __half* __restrict__ out,
    long validElems, long total8) {
    long i = (long)b * 256 + threadIdx.x;
    if (i >= total8) return;
    long e = i * 8;
    __half2 h[4];
    if (e + 8 <= validElems) {
        float4 a = *reinterpret_cast<const float4*>(in + e);
        float4 bb = *reinterpret_cast<const float4*>(in + e + 4);
        h[0] = __floats2half2_rn(a.x, a.y);
        h[1] = __floats2half2_rn(a.z, a.w);
        h[2] = __floats2half2_rn(bb.x, bb.y);
        h[3] = __floats2half2_rn(bb.z, bb.w);
    } else {
        h[0] = h[1] = h[2] = h[3] = __floats2half2_rn(0.f, 0.f);
    }
    __half2* dst = reinterpret_cast<__half2*>(out + e);
    dst[0] = h[0]; dst[1] = h[1]; dst[2] = h[2]; dst[3] = h[3];
}

__device__ __forceinline__ void aux_convert_cols(
    int b, const float* __restrict__ in, __half* __restrict__ out,
    int C, int ldo, int colOff, int total8) {
    int i = b * 256 + threadIdx.x;
    if (i >= total8) return;
    long e = (long)i * 8;
    int k = (int)(e / C);
    int c = (int)(e - (long)k * C);
    float4 a = *reinterpret_cast<const float4*>(in + e);
    float4 bb = *reinterpret_cast<const float4*>(in + e + 4);
    __half2* dst = reinterpret_cast<__half2*>(out + (size_t)k * ldo + colOff + c);
    dst[0] = __floats2half2_rn(a.x, a.y);
    dst[1] = __floats2half2_rn(a.z, a.w);
    dst[2] = __floats2half2_rn(bb.x, bb.y);
    dst[3] = __floats2half2_rn(bb.z, bb.w);
}

__device__ __forceinline__ void aux_concat2(
    int b, const float* __restrict__ a, const float* __restrict__ bsrc,
    float* __restrict__ o, int n) {
    int i = b * 256 + threadIdx.x;
    if (i < n) o[i] = a[i];
    else if (i < 2 * n) o[i] = bsrc[i - n];
}

// Per-block mask-dtype probe: scan first 2048 words (L2-cached after first
// block). Deterministic; replaces the separate probe launch.
__device__ __forceinline__ int probe_mode_block(const unsigned int* w) {
    __shared__ int s_other, s_f1, s_i1;
    if (threadIdx.x == 0) { s_other = 0; s_f1 = 0; s_i1 = 0; }
    __syncthreads();
    int lo = 0, lf = 0, li = 0;
    for (int i = threadIdx.x; i < 2048; i += blockDim.x) {
        unsigned v = w[i];
        if (v == 0u) continue;
        else if (v == 1u) li++;
        else if (v == 0x3F800000u) lf++;
        else lo++;
    }
    atomicAdd(&s_other, lo); atomicAdd(&s_f1, lf); atomicAdd(&s_i1, li);
    __syncthreads();
    if (s_other > 64) return 0;
    return (s_f1 >= s_i1) ? 2 : 1;
}

// ---------------------------------------------------------------------------
// MEGA kernel: split-K gemm1 (256 CTAs) + remaining prep work
// ---------------------------------------------------------------------------
#define MEGA_GEMM 256
#define AUX_RED   79
#define AUX_W2    256
#define AUX_WLR1  256
#define AUX_WLR2  256
#define AUX_BLR   8
#define AUX_W4    10000
#define AUX_W6    10000
#define MEGA_BLOCKS (MEGA_GEMM + AUX_RED + AUX_W2 + AUX_WLR1 + AUX_WLR2 + \
                     AUX_BLR + AUX_W4 + AUX_W6)

__global__ __launch_bounds__(256, 2)
void mega_kernel(const __half* __restrict__ noisyh,
                 const __half* __restrict__ W1c, float* __restrict__ psum,
                 const float* __restrict__ part, float* __restrict__ out_pop,
                 const float* __restrict__ enc_w2, __half* __restrict__ W2c,
                 const float* __restrict__ lk_w1, const float* __restrict__ rc_w1,
                 __half* __restrict__ Wlr,
                 const float* __restrict__ lk_b1, const float* __restrict__ rc_b1,
                 float* __restrict__ blr,
                 const float* __restrict__ lk_w2, __half* __restrict__ W4c,
                 const float* __restrict__ rc_w2, __half* __restrict__ W6c) {
    extern __shared__ __align__(128) char smem[];
    int bid = blockIdx.x;
    if (bid < MEGA_GEMM) {
        int z = bid >> 7;            // K split 0/1
        int bx = bid & 15;           // m tile
        int by = (bid >> 4) & 7;     // n tile
        const __half* A = noisyh + (size_t)z * KHALF;
        const __half* B = W1c + (size_t)z * KHALF * HID;
        float* C = psum + (size_t)z * BATCH * HID;
        gemm_body<ACT_NONE, false, false, true>(
            A, B, nullptr, C, BATCH, HID, KHALF, KPAD, HID, bx, by, smem);
        return;
    }
    int aux = bid - MEGA_GEMM;
    if (aux < AUX_RED) { aux_popular_reduce(aux, part, out_pop); return; }
    aux -= AUX_RED;
    if (aux < AUX_W2) {
        aux_convert_pad(aux, enc_w2, W2c, (long)HID * EMB, (long)HID * EMB / 8);
        return;
    }
    aux -= AUX_W2;
    if (aux < AUX_WLR1) {
        aux_convert_cols(aux, lk_w1, Wlr, HID, 2 * HID, 0, EMB * HID / 8);
        return;
    }
    aux -= AUX_WLR1;
    if (aux < AUX_WLR2) {
        aux_convert_cols(aux, rc_w1, Wlr, HID, 2 * HID, HID, EMB * HID / 8);
        return;
    }
    aux -= AUX_WLR2;
    if (aux < AUX_BLR) { aux_concat2(aux, lk_b1, rc_b1, blr, HID); return; }
    aux -= AUX_BLR;
    if (aux < AUX_W4) {
        aux_convert_pad(aux, lk_w2, W4c, (long)HID * NITEMS,
                        (long)HID * NITEMS / 8);
        return;
    }
    aux -= AUX_W4;
    aux_convert_pad(aux, rc_w2, W6c, (long)HID * NITEMS,
                    (long)HID * NITEMS / 8);
}

// ---------------------------------------------------------------------------
// Merged prep: premask+popular partials (w/ per-block mask probe) + W1 convert
// ---------------------------------------------------------------------------
#define PREM_X 79                       // ceil(KPAD/256)
#define PREM_BLOCKS (PREM_X * 16)       // 1264
#define W1_BLOCKS ((KPAD * HID / 8) / 256)  // 10048
#define PREP_BLOCKS (PREM_BLOCKS + W1_BLOCKS)

__global__ void prep_kernel(const float* __restrict__ likes,
                            const void* __restrict__ mask,
                            __half* __restrict__ noisy,
                            float* __restrict__ part,
                            const float* __restrict__ enc_w1,
                            __half* __restrict__ W1c) {
    int bid = blockIdx.x;
    if (bid >= PREM_BLOCKS) {
        aux_convert_pad(bid - PREM_BLOCKS, enc_w1, W1c,
                        (long)NITEMS * HID, (long)KPAD * HID / 8);
        return;
    }
    const int mode = probe_mode_block((const unsigned int*)mask);
    const int col = (bid % PREM_X) * 256 + threadIdx.x;
    if (col >= KPAD) return;
    const int r0 = (bid / PREM_X) * 128;

    if (col >= NITEMS) {  // padding region: zero noisy, no popular
        const __half hz = __float2half_rn(0.f);
        for (int r = 0; r < 128; r++)
            noisy[(size_t)(r0 + r) * KPAD + col] = hz;
        return;
    }

    const unsigned char* m8 = (const unsigned char*)mask;
    const int*           mi = (const int*)mask;
    const float*         mf = (const float*)mask;

    float sum = 0.f;
    #pragma unroll 4
    for (int r = 0; r < 128; r++) {
        size_t e = (size_t)(r0 + r) * NITEMS + col;
        float v = likes[e];
        sum += v;
        bool drop;
        if (mode == 0)      drop = (m8[e] != 0);
        else if (mode == 1) drop = (mi[e] != 0);
        else                drop = (mf[e] != 0.f);
        noisy[(size_t)(r0 + r) * KPAD + col] = __float2half_rn(drop ? 0.f : v);
    }
    part[(bid / PREM_X) * NITEMS + col] = sum;
}

// combine split-K partials: Hh = fp16(relu(p0 + p1 + bias))
__global__ void combine_splitk_kernel(const float* __restrict__ p,
                                      const float* __restrict__ bias,
                                      __half* __restrict__ out) {
    const size_t MN = (size_t)BATCH * HID;
    size_t e = ((size_t)blockIdx.x * 256 + threadIdx.x) * 4;
    if (e >= MN) return;
    int col = (int)(e & (HID - 1));
    float4 a = *reinterpret_cast<const float4*>(p + e);
    float4 b = *reinterpret_cast<const float4*>(p + MN + e);
    float4 bb = *reinterpret_cast<const float4*>(bias + col);
    float x0 = fmaxf(a.x + b.x + bb.x, 0.f);
    float x1 = fmaxf(a.y + b.y + bb.y, 0.f);
    float x2 = fmaxf(a.z + b.z + bb.z, 0.f);
    float x3 = fmaxf(a.w + b.w + bb.w, 0.f);
    __half2* dst = reinterpret_cast<__half2*>(out + e);
    dst[0] = __floats2half2_rn(x0, x1);
    dst[1] = __floats2half2_rn(x2, x3);
}

// per-row l2 normalize; emit fp16 normalized AND fp16 copy of E
__global__ void norm_half_kernel(const float* __restrict__ E,
                                 __half* __restrict__ Nrmh,
                                 __half* __restrict__ Eh) {
    int row = blockIdx.x;
    int t = threadIdx.x;
    float4 v = reinterpret_cast<const float4*>(E + (size_t)row * EMB)[t];
    float ss = v.x * v.x + v.y * v.y + v.z * v.z + v.w * v.w;
    #pragma unroll
    for (int o = 16; o > 0; o >>= 1)
        ss += __shfl_xor_sync(0xFFFFFFFFu, ss, o);
    __shared__ float ws[4];
    if ((t & 31) == 0) ws[t >> 5] = ss;
    __syncthreads();
    float tot = ws[0] + ws[1] + ws[2] + ws[3];
    float inv = rsqrtf(fmaxf(tot, 1e-12f));
    __half2* eh = reinterpret_cast<__half2*>(Eh + (size_t)row * EMB + t * 4);
    eh[0] = __floats2half2_rn(v.x, v.y);
    eh[1] = __floats2half2_rn(v.z, v.w);
    __half2* nh = reinterpret_cast<__half2*>(Nrmh + (size_t)row * EMB + t * 4);
    nh[0] = __floats2half2_rn(v.x * inv, v.y * inv);
    nh[1] = __floats2half2_rn(v.z * inv, v.w * inv);
}

#define NO_DUAL nullptr, nullptr, nullptr, nullptr, 0x40000000

// ---------------------------------------------------------------------------
// Launch
// ---------------------------------------------------------------------------
extern "C" void kernel_launch(void* const* d_in, const int* in_sizes, int n_in,
                              void* d_out, int out_size) {
    const float* likes  = (const float*)d_in[1];
    const void*  nmask  = d_in[2];
    const float* enc_w1 = (const float*)d_in[3];
    const float* enc_b1 = (const float*)d_in[4];
    const float* enc_w2 = (const float*)d_in[5];
    const float* enc_b2 = (const float*)d_in[6];
    const float* lk_w1  = (const float*)d_in[7];
    const float* lk_b1  = (const float*)d_in[8];
    const float* lk_w2  = (const float*)d_in[9];
    const float* lk_b2  = (const float*)d_in[10];
    const float* rc_w1  = (const float*)d_in[11];
    const float* rc_b1  = (const float*)d_in[12];
    const float* rc_w2  = (const float*)d_in[13];
    const float* rc_b2  = (const float*)d_in[14];

    float* out       = (float*)d_out;
    float* out_likes = out;
    float* out_sim   = out_likes + (size_t)BATCH * NITEMS;
    float* out_rec   = out_sim + (size_t)BATCH * BATCH;
    float* out_pop   = out_rec + (size_t)BATCH * NITEMS;

    __half *noisyh, *W1c, *W2c, *Wlr, *W4c, *W6c, *Hh, *Hh2, *Eh, *Nrmh;
    float *E, *part, *blr, *psum;
    cudaGetSymbolAddress((void**)&noisyh, g_noisyh);
    cudaGetSymbolAddress((void**)&W1c, g_W1c);
    cudaGetSymbolAddress((void**)&W2c, g_W2c);
    cudaGetSymbolAddress((void**)&Wlr, g_Wlr);
    cudaGetSymbolAddress((void**)&W4c, g_W4c);
    cudaGetSymbolAddress((void**)&W6c, g_W6c);
    cudaGetSymbolAddress((void**)&blr, g_blr);
    cudaGetSymbolAddress((void**)&psum, g_psum);
    cudaGetSymbolAddress((void**)&Hh, g_Hh);
    cudaGetSymbolAddress((void**)&Hh2, g_Hh2);
    cudaGetSymbolAddress((void**)&E, g_E);
    cudaGetSymbolAddress((void**)&Eh, g_Eh);
    cudaGetSymbolAddress((void**)&Nrmh, g_Nrmh);
    cudaGetSymbolAddress((void**)&part, g_part);

    const int smem = NSTAGE * SSZ;      // 96KB (BN=128 body)
    const int smem64 = NSTAGE * SSZ64;  // 72KB (BN=64 body)
    cudaFuncSetAttribute(mega_kernel,
                         cudaFuncAttributeMaxDynamicSharedMemorySize, smem);
    cudaFuncSetAttribute(simhid_kernel,
                         cudaFuncAttributeMaxDynamicSharedMemorySize, smem);
    cudaFuncSetAttribute(gemm2_kernel,
                         cudaFuncAttributeMaxDynamicSharedMemorySize, smem64);
    cudaFuncSetAttribute(hmma_gemm<ACT_SIG, true, false, true>,
                         cudaFuncAttributeMaxDynamicSharedMemorySize, smem);

    // 1: merged prep -- denoise+popular partials (self-probing) + W1 convert
    prep_kernel<<<PREP_BLOCKS, 256>>>(likes, nmask, noisyh, part, enc_w1, W1c);
    // 2: MEGA -- split-K gemm1 + all remaining independent prep work
    mega_kernel<<<MEGA_BLOCKS, 256, smem>>>(
        noisyh, W1c, psum, part, out_pop,
        enc_w2, W2c, lk_w1, rc_w1, Wlr, lk_b1, rc_b1, blr,
        lk_w2, W4c, rc_w2, W6c);
    // 3: combine partials -> Hh = fp16(relu(p0+p1+b1))
    combine_splitk_kernel<<<(int)(((size_t)BATCH * HID / 4 + 255) / 256), 256>>>(
        psum, enc_b1, Hh);

    // 4: encoder layer 2 (128x64 tiles -> 128 CTAs, 2x parallelism)
    gemm2_kernel<<<dim3(BATCH / 128, EMB / 64), 256, smem64>>>(
        Hh, W2c, enc_b2, E);
    // 5: norm
    norm_half_kernel<<<BATCH, 128>>>(E, Nrmh, Eh);

    // 6: merged sim + head-hidden (512 CTAs)
    simhid_kernel<<<512, 256, smem>>>(Nrmh, out_sim, Eh, Wlr, blr, Hh2);

    // 7: BOTH head outputs in ONE launch (wave merge)
    const int nTiles = (NITEMS + 127) / 128;  // 157
    hmma_gemm<ACT_SIG, true, false, true>
        <<<dim3(BATCH / 128, 2 * nTiles), 256, smem>>>(
        Hh2, W4c, lk_b2, out_likes, BATCH, NITEMS, HID, 2 * HID, NITEMS,
        Hh2 + HID, W6c, rc_b2, out_rec, nTiles);
}

// round 16
// speedup vs baseline: 1.2219x; 1.0069x over previous
#include <cuda_runtime.h>
#include <cuda_fp16.h>
#include <cstdint>

// Problem constants
#define BATCH  2048
#define NITEMS 20000
#define KPAD   20096   // NITEMS padded to 2 x 10048 (157 x 64 per K-split)
#define KHALF  10048
#define EMB    512
#define HID    1024    // 2*D

// ---------------------------------------------------------------------------
// Scratch (no allocations -> __device__ globals)
// ---------------------------------------------------------------------------
__device__ __half g_noisyh[(size_t)BATCH * KPAD];    // masked likes fp16, padded
__device__ __half g_W1c[(size_t)KPAD * HID];         // enc_w1 fp16 [20096][1024]
__device__ __half g_W2c[(size_t)HID * EMB];          // enc_w2 fp16 [1024][512]
__device__ __half g_Wlr[(size_t)EMB * (2 * HID)];    // [512][2048] = lk_w1 ++ rc_w1
__device__ __half g_W4c[(size_t)HID * NITEMS];       // lk_w2 fp16 [1024][20000]
__device__ __half g_W6c[(size_t)HID * NITEMS];       // rc_w2 fp16 [1024][20000]
__device__ float  g_blr[2 * HID];                    // lk_b1 ++ rc_b1
__device__ float  g_psum[2 * (size_t)BATCH * HID];   // split-K partials (f32)
__device__ __half g_Hh[(size_t)BATCH * HID];         // encoder hidden fp16
__device__ __half g_Hh2[(size_t)BATCH * 2 * HID];    // fused head hiddens fp16
__device__ float  g_E[(size_t)BATCH * EMB];          // embed f32
__device__ __half g_Eh[(size_t)BATCH * EMB];         // embed fp16
__device__ __half g_Nrmh[(size_t)BATCH * EMB];       // normalized fp16
__device__ float  g_part[16 * NITEMS];

// ---------------------------------------------------------------------------
// PTX helpers (arch-generic sm_80-era instructions)
// ---------------------------------------------------------------------------
__device__ __forceinline__ uint32_t smem_u32(const void* p) {
    uint32_t a;
    asm("{ .reg .u64 t; cvta.to.shared.u64 t, %1; cvt.u32.u64 %0, t; }"
        : "=r"(a) : "l"(p));
    return a;
}
__device__ __forceinline__ void cp16(uint32_t dst, const void* src, int sz) {
    asm volatile("cp.async.cg.shared.global [%0], [%1], 16, %2;"
        :: "r"(dst), "l"(src), "r"(sz));
}
#define CP_COMMIT() asm volatile("cp.async.commit_group;" ::: "memory")
#define CP_WAIT(n)  asm volatile("cp.async.wait_group %0;" :: "n"(n) : "memory")

#define LDSM_X4(r, addr) \
    asm volatile("ldmatrix.sync.aligned.m8n8.x4.shared.b16 {%0,%1,%2,%3}, [%4];" \
        : "=r"((r)[0]), "=r"((r)[1]), "=r"((r)[2]), "=r"((r)[3]) : "r"(addr))

#define LDSM_X4_T(r, addr) \
    asm volatile("ldmatrix.sync.aligned.m8n8.x4.trans.shared.b16 {%0,%1,%2,%3}, [%4];" \
        : "=r"((r)[0]), "=r"((r)[1]), "=r"((r)[2]), "=r"((r)[3]) : "r"(addr))

__device__ __forceinline__ void mma16816(float* d, const uint32_t* a,
                                         uint32_t b0, uint32_t b1) {
    asm volatile(
        "mma.sync.aligned.m16n8k16.row.col.f32.f16.f16.f32 "
        "{%0,%1,%2,%3}, {%4,%5,%6,%7}, {%8,%9}, {%0,%1,%2,%3};"
        : "+f"(d[0]), "+f"(d[1]), "+f"(d[2]), "+f"(d[3])
        : "r"(a[0]), "r"(a[1]), "r"(a[2]), "r"(a[3]), "r"(b0), "r"(b1));
}

enum { ACT_RELU = 0, ACT_SIG = 1, ACT_NEG = 2, ACT_NONE = 3 };
#define BK 64
#define NSTAGE 3
#define ASZ 16384                 // A: 128 rows * 128B ; B(trans): 64 rows * 256B
#define SSZ 32768                 // A + B per stage (BN=128 body)

// ---------------------------------------------------------------------------
// GEMM body, CTA tile 128x128, 8 warps of 64x32, occ 2. (R13-proven)
// Single __syncthreads per K-chunk; 3 stages, prefetch distance 2.
// MIRROR (sim only): also write the transposed tile (symmetric output).
// ---------------------------------------------------------------------------
template<int ACT, bool HAS_BIAS, bool OUT_HALF, bool TRANSB, bool MIRROR = false>
__device__ __forceinline__ void gemm_body(
    const __half* __restrict__ A, const __half* __restrict__ Bt,
    const float* __restrict__ bias, void* __restrict__ Cout,
    int M, int N, int K, int lda, int ldb, int bx, int by, char* smem,
    bool do_mirror = false) {
    const uint32_t sbase = smem_u32(smem);

    const int tid = threadIdx.x;
    const int lane = tid & 31, wid = tid >> 5;
    const int wm = (wid & 1) * 64;
    const int wn = (wid >> 1) * 32;
    const int m0 = bx * 128;
    const int n0 = by * 128;
    const int nch = K / BK;

    float acc[4][4][4];
    #pragma unroll
    for (int i = 0; i < 4; i++)
        #pragma unroll
        for (int j = 0; j < 4; j++)
            #pragma unroll
            for (int q = 0; q < 4; q++) acc[i][j][q] = 0.f;

    auto load_stage = [&](int ch, int st) {
        const int k0 = ch * BK;
        const uint32_t sA = sbase + st * SSZ;
        const uint32_t sB = sA + ASZ;
        #pragma unroll
        for (int u = 0; u < 4; u++) {
            int idx = tid + u * 256;
            int r = idx >> 3, c = idx & 7;
            const __half* src = A + (size_t)(m0 + r) * lda + k0 + c * 8;
            cp16(sA + r * 128 + ((c ^ (r & 7)) << 4), src, 16);
        }
        if constexpr (!TRANSB) {
            #pragma unroll
            for (int u = 0; u < 4; u++) {
                int idx = tid + u * 256;
                int r = idx >> 3, c = idx & 7;
                int n = n0 + r;
                const __half* src = Bt + (size_t)n * ldb + k0 + c * 8;
                cp16(sB + r * 128 + ((c ^ (r & 7)) << 4), src, (n < N) ? 16 : 0);
            }
        } else {
            // B tile [BK=64 k-rows][128 n], 256B per k-row, per-128B-half swizzle
            #pragma unroll
            for (int u = 0; u < 4; u++) {
                int idx = tid + u * 256;
                int k = idx >> 4, c = idx & 15;
                const __half* src = Bt + (size_t)(k0 + k) * ldb + n0 + c * 8;
                uint32_t dst = sB + k * 256 + ((c >> 3) << 7)
                             + (((c & 7) ^ (k & 7)) << 4);
                cp16(dst, src, (n0 + c * 8 + 8 <= N) ? 16 : 0);
            }
        }
        CP_COMMIT();
    };

    const int aRow = wm + (lane & 15);
    const int aKsel = lane >> 4;
    const int swz = lane & 7;
    const int bRow = wn + ((lane >> 4) << 3) + (lane & 7);
    const int bKsel = (lane >> 3) & 1;
    const int kLane = ((lane >> 3) & 1) * 8 + (lane & 7);
    int bOffT0 = 0, bOffT1 = 0;
    {
        int n0l = wn + ((lane >> 4) << 3);
        int c0 = n0l >> 3, c1 = (n0l + 16) >> 3;
        bOffT0 = ((c0 >> 3) << 7) + (((c0 & 7) ^ (lane & 7)) << 4);
        bOffT1 = ((c1 >> 3) << 7) + (((c1 & 7) ^ (lane & 7)) << 4);
    }

    load_stage(0, 0);
    load_stage(1, 1);

    for (int i = 0; i < nch; i++) {
        CP_WAIT(1);
        __syncthreads();
        const int j = i + 2;
        if (j < nch) load_stage(j, j % NSTAGE);
        else         CP_COMMIT();

        const uint32_t sA = sbase + (i % NSTAGE) * SSZ;
        const uint32_t sB = sA + ASZ;
        #pragma unroll
        for (int kk = 0; kk < 4; kk++) {
            uint32_t a[4][4], b[2][4];
            const uint32_t aByte = ((2 * kk + aKsel) ^ swz) << 4;
            #pragma unroll
            for (int mf = 0; mf < 4; mf++)
                LDSM_X4(a[mf], sA + (aRow + 16 * mf) * 128 + aByte);
            if constexpr (!TRANSB) {
                const uint32_t bByte = ((2 * kk + bKsel) ^ swz) << 4;
                #pragma unroll
                for (int nf2 = 0; nf2 < 2; nf2++)
                    LDSM_X4(b[nf2], sB + (bRow + 16 * nf2) * 128 + bByte);
            } else {
                const uint32_t rowB = sB + (kk * 16 + kLane) * 256;
                LDSM_X4_T(b[0], rowB + bOffT0);
                LDSM_X4_T(b[1], rowB + bOffT1);
            }
            #pragma unroll
            for (int mf = 0; mf < 4; mf++)
                #pragma unroll
                for (int nf = 0; nf < 4; nf++)
                    mma16816(acc[mf][nf], a[mf],
                             b[nf >> 1][(nf & 1) * 2],
                             b[nf >> 1][(nf & 1) * 2 + 1]);
        }
    }

    #pragma unroll
    for (int mf = 0; mf < 4; mf++) {
        const int row = m0 + wm + mf * 16 + (lane >> 2);
        #pragma unroll
        for (int nf = 0; nf < 4; nf++) {
            const int col = n0 + wn + nf * 8 + 2 * (lane & 3);
            if (col >= N) continue;
            float2 lo = make_float2(acc[mf][nf][0], acc[mf][nf][1]);
            float2 hi = make_float2(acc[mf][nf][2], acc[mf][nf][3]);
            if (HAS_BIAS) {
                float2 bb = *reinterpret_cast<const float2*>(bias + col);
                lo.x += bb.x; lo.y += bb.y;
                hi.x += bb.x; hi.y += bb.y;
            }
            if (ACT == ACT_RELU) {
                lo.x = fmaxf(lo.x, 0.f); lo.y = fmaxf(lo.y, 0.f);
                hi.x = fmaxf(hi.x, 0.f); hi.y = fmaxf(hi.y, 0.f);
            } else if (ACT == ACT_SIG) {
                lo.x = __fdividef(1.f, 1.f + __expf(-lo.x));
                lo.y = __fdividef(1.f, 1.f + __expf(-lo.y));
                hi.x = __fdividef(1.f, 1.f + __expf(-hi.x));
                hi.y = __fdividef(1.f, 1.f + __expf(-hi.y));
            } else if (ACT == ACT_NEG) {
                lo.x = -lo.x; lo.y = -lo.y;
                hi.x = -hi.x; hi.y = -hi.y;
            }
            if (OUT_HALF) {
                __half* C = (__half*)Cout;
                *reinterpret_cast<__half2*>(C + (size_t)row * N + col) =
                    __floats2half2_rn(lo.x, lo.y);
                *reinterpret_cast<__half2*>(C + (size_t)(row + 8) * N + col) =
                    __floats2half2_rn(hi.x, hi.y);
            } else {
                float* C = (float*)Cout;
                *reinterpret_cast<float2*>(C + (size_t)row * N + col) = lo;
                *reinterpret_cast<float2*>(C + (size_t)(row + 8) * N + col) = hi;
                if (MIRROR && do_mirror) {
                    // transposed writes: same values, bitwise-identical math
                    C[(size_t)col * N + row]           = lo.x;
                    C[(size_t)(col + 1) * N + row]     = lo.y;
                    C[(size_t)col * N + row + 8]       = hi.x;
                    C[(size_t)(col + 1) * N + row + 8] = hi.y;
                }
            }
        }
    }
}

// ---------------------------------------------------------------------------
// GEMM body, CTA tile 128x64, TRANSB only (R14-proven geometry). Used for the
// small encoder-layer-2 GEMM to double its CTA parallelism.
// ---------------------------------------------------------------------------
#define BSZ64 8192
#define SSZ64 (ASZ + BSZ64)

template<int ACT, bool HAS_BIAS, bool OUT_HALF>
__device__ __forceinline__ void gemm_body64(
    const __half* __restrict__ A, const __half* __restrict__ Bt,
    const float* __restrict__ bias, void* __restrict__ Cout,
    int M, int N, int K, int lda, int ldb, int bx, int by, char* smem) {
    const uint32_t sbase = smem_u32(smem);

    const int tid = threadIdx.x;
    const int lane = tid & 31, wid = tid >> 5;
    const int wm = (wid & 3) * 32;        // 4 m-warps
    const int wn = (wid >> 2) * 32;       // 2 n-warps
    const int m0 = bx * 128;
    const int n0 = by * 64;
    const int nch = K / BK;

    float acc[2][4][4];
    #pragma unroll
    for (int i = 0; i < 2; i++)
        #pragma unroll
        for (int j = 0; j < 4; j++)
            #pragma unroll
            for (int q = 0; q < 4; q++) acc[i][j][q] = 0.f;

    auto load_stage = [&](int ch, int st) {
        const int k0 = ch * BK;
        const uint32_t sA = sbase + st * SSZ64;
        const uint32_t sB = sA + ASZ;
        #pragma unroll
        for (int u = 0; u < 4; u++) {
            int idx = tid + u * 256;
            int r = idx >> 3, c = idx & 7;
            const __half* src = A + (size_t)(m0 + r) * lda + k0 + c * 8;
            cp16(sA + r * 128 + ((c ^ (r & 7)) << 4), src, 16);
        }
        #pragma unroll
        for (int u = 0; u < 2; u++) {
            int idx = tid + u * 256;
            int k = idx >> 3, c = idx & 7;
            const __half* src = Bt + (size_t)(k0 + k) * ldb + n0 + c * 8;
            uint32_t dst = sB + k * 128 + ((c ^ (k & 7)) << 4);
            cp16(dst, src, (n0 + c * 8 + 8 <= N) ? 16 : 0);
        }
        CP_COMMIT();
    };

    const int aRow = wm + (lane & 15);
    const int aKsel = lane >> 4;
    const int swz = lane & 7;
    const int kLane = ((lane >> 3) & 1) * 8 + (lane & 7);
    int bOffT0 = 0, bOffT1 = 0;
    {
        int n0l = wn + ((lane >> 4) << 3);
        int c0 = n0l >> 3, c1 = (n0l + 16) >> 3;
        bOffT0 = ((c0 ^ (lane & 7)) << 4);
        bOffT1 = ((c1 ^ (lane & 7)) << 4);
    }

    load_stage(0, 0);
    load_stage(1, 1);

    for (int i = 0; i < nch; i++) {
        CP_WAIT(1);
        __syncthreads();
        const int j = i + 2;
        if (j < nch) load_stage(j, j % NSTAGE);
        else         CP_COMMIT();

        const uint32_t sA = sbase + (i % NSTAGE) * SSZ64;
        const uint32_t sB = sA + ASZ;
        #pragma unroll
        for (int kk = 0; kk < 4; kk++) {
            uint32_t a[2][4], b[2][4];
            const uint32_t aByte = ((2 * kk + aKsel) ^ swz) << 4;
            #pragma unroll
            for (int mf = 0; mf < 2; mf++)
                LDSM_X4(a[mf], sA + (aRow + 16 * mf) * 128 + aByte);
            const uint32_t rowB = sB + (kk * 16 + kLane) * 128;
            LDSM_X4_T(b[0], rowB + bOffT0);
            LDSM_X4_T(b[1], rowB + bOffT1);
            #pragma unroll
            for (int mf = 0; mf < 2; mf++)
                #pragma unroll
                for (int nf = 0; nf < 4; nf++)
                    mma16816(acc[mf][nf], a[mf],
                             b[nf >> 1][(nf & 1) * 2],
                             b[nf >> 1][(nf & 1) * 2 + 1]);
        }
    }

    #pragma unroll
    for (int mf = 0; mf < 2; mf++) {
        const int row = m0 + wm + mf * 16 + (lane >> 2);
        #pragma unroll
        for (int nf = 0; nf < 4; nf++) {
            const int col = n0 + wn + nf * 8 + 2 * (lane & 3);
            if (col >= N) continue;
            float2 lo = make_float2(acc[mf][nf][0], acc[mf][nf][1]);
            float2 hi = make_float2(acc[mf][nf][2], acc[mf][nf][3]);
            if (HAS_BIAS) {
                float2 bb = *reinterpret_cast<const float2*>(bias + col);
                lo.x += bb.x; lo.y += bb.y;
                hi.x += bb.x; hi.y += bb.y;
            }
            if (ACT == ACT_RELU) {
                lo.x = fmaxf(lo.x, 0.f); lo.y = fmaxf(lo.y, 0.f);
                hi.x = fmaxf(hi.x, 0.f); hi.y = fmaxf(hi.y, 0.f);
            }
            if (OUT_HALF) {
                __half* C = (__half*)Cout;
                *reinterpret_cast<__half2*>(C + (size_t)row * N + col) =
                    __floats2half2_rn(lo.x, lo.y);
                *reinterpret_cast<__half2*>(C + (size_t)(row + 8) * N + col) =
                    __floats2half2_rn(hi.x, hi.y);
            } else {
                float* C = (float*)Cout;
                *reinterpret_cast<float2*>(C + (size_t)row * N + col) = lo;
                *reinterpret_cast<float2*>(C + (size_t)(row + 8) * N + col) = hi;
            }
        }
    }
}

// ---------------------------------------------------------------------------
// Standalone GEMM kernels
// ---------------------------------------------------------------------------
template<int ACT, bool HAS_BIAS, bool OUT_HALF, bool TRANSB>
__global__ __launch_bounds__(256, 2)
void hmma_gemm(const __half* __restrict__ Ap, const __half* __restrict__ Bp,
               const float* __restrict__ biasp, void* __restrict__ Coutp,
               int M, int N, int K, int lda, int ldb,
               const __half* A2, const __half* B2,
               const float* bias2, void* Cout2, int nSplit) {
    extern __shared__ __align__(128) char smem[];
    const __half* A   = Ap;
    const __half* Bt  = Bp;
    const float* bias = biasp;
    void* Cout        = Coutp;
    int by = blockIdx.y;
    if (by >= nSplit) {
        by -= nSplit;
        A = A2; Bt = B2; bias = bias2; Cout = Cout2;
    }
    gemm_body<ACT, HAS_BIAS, OUT_HALF, TRANSB>(
        A, Bt, bias, Cout, M, N, K, lda, ldb, blockIdx.x, by, smem);
}

// encoder layer 2 with 128x64 tiles (128 CTAs)
__global__ __launch_bounds__(256, 2)
void gemm2_kernel(const __half* __restrict__ Hh, const __half* __restrict__ W2c,
                  const float* __restrict__ enc_b2, float* __restrict__ E) {
    extern __shared__ __align__(128) char smem[];
    gemm_body64<ACT_RELU, true, false>(
        Hh, W2c, enc_b2, E, BATCH, EMB, HID, HID, EMB,
        blockIdx.x, blockIdx.y, smem);
}

// merged sim (upper triangle only, mirrored) + head-hidden.
// sim tiles: 136 upper-triangle pairs (i<=j); hid: 256 CTAs. Total 392.
__global__ __launch_bounds__(256, 2)
void simhid_kernel(const __half* __restrict__ Nrmh, float* __restrict__ out_sim,
                   const __half* __restrict__ Eh, const __half* __restrict__ Wlr,
                   const float* __restrict__ blr, __half* __restrict__ Hh2) {
    extern __shared__ __align__(128) char smem[];
    int bid = blockIdx.x;
    if (bid < 136) {
        // map bid -> upper-triangle pair (i, j), i <= j, 16x16 tile grid
        int i = 0, t = bid;
        while (t >= 16 - i) { t -= 16 - i; i++; }
        int j = i + t;
        gemm_body<ACT_NEG, false, false, false, true>(
            Nrmh, Nrmh, nullptr, out_sim, BATCH, BATCH, EMB, EMB, EMB,
            i, j, smem, i != j);
    } else {
        bid -= 136;
        gemm_body<ACT_RELU, true, true, true>(
            Eh, Wlr, blr, Hh2, BATCH, 2 * HID, EMB, EMB, 2 * HID,
            bid & 15, bid >> 4, smem);
    }
}

// ---------------------------------------------------------------------------
// Aux device helpers
// ---------------------------------------------------------------------------
__device__ __forceinline__ void aux_popular_reduce(
    int b, const float* __restrict__ part, float* __restrict__ out_pop) {
    int i = b * 256 + threadIdx.x;
    if (i >= NITEMS) return;
    float s = 0.f;
    #pragma unroll
    for (int c = 0; c < 16; c++) s += part[c * NITEMS + i];
    out_pop[i] = s * (1.0f / (float)BATCH);
}

__device__ __forceinline__ void aux_convert_pad(
    int b, const float* __restrict__ in, __half* __restrict__ out,
    long validElems, long total8) {
    long i = (long)b * 256 + threadIdx.x;
    if (i >= total8) return;
    long e = i * 8;
    __half2 h[4];
    if (e + 8 <= validElems) {
        float4 a = *reinterpret_cast<const float4*>(in + e);
        float4 bb = *reinterpret_cast<const float4*>(in + e + 4);
        h[0] = __floats2half2_rn(a.x, a.y);
        h[1] = __floats2half2_rn(a.z, a.w);
        h[2] = __floats2half2_rn(bb.x, bb.y);
        h[3] = __floats2half2_rn(bb.z, bb.w);
    } else {
        h[0] = h[1] = h[2] = h[3] = __floats2half2_rn(0.f, 0.f);
    }
    __half2* dst = reinterpret_cast<__half2*>(out + e);
    dst[0] = h[0]; dst[1] = h[1]; dst[2] = h[2]; dst[3] = h[3];
}

__device__ __forceinline__ void aux_convert_cols(
    int b, const float* __restrict__ in, __half* __restrict__ out,
    int C, int ldo, int colOff, int total8) {
    int i = b * 256 + threadIdx.x;
    if (i >= total8) return;
    long e = (long)i * 8;
    int k = (int)(e / C);
    int c = (int)(e - (long)k * C);
    float4 a = *reinterpret_cast<const float4*>(in + e);
    float4 bb = *reinterpret_cast<const float4*>(in + e + 4);
    __half2* dst = reinterpret_cast<__half2*>(out + (size_t)k * ldo + colOff + c);
    dst[0] = __floats2half2_rn(a.x, a.y);
    dst[1] = __floats2half2_rn(a.z, a.w);
    dst[2] = __floats2half2_rn(bb.x, bb.y);
    dst[3] = __floats2half2_rn(bb.z, bb.w);
}

__device__ __forceinline__ void aux_concat2(
    int b, const float* __restrict__ a, const float* __restrict__ bsrc,
    float* __restrict__ o, int n) {
    int i = b * 256 + threadIdx.x;
    if (i < n) o[i] = a[i];
    else if (i < 2 * n) o[i] = bsrc[i - n];
}

// Per-block mask-dtype probe (first 2048 words; L2-cached after first block)
__device__ __forceinline__ int probe_mode_block(const unsigned int* w) {
    __shared__ int s_other, s_f1, s_i1;
    if (threadIdx.x == 0) { s_other = 0; s_f1 = 0; s_i1 = 0; }
    __syncthreads();
    int lo = 0, lf = 0, li = 0;
    for (int i = threadIdx.x; i < 2048; i += blockDim.x) {
        unsigned v = w[i];
        if (v == 0u) continue;
        else if (v == 1u) li++;
        else if (v == 0x3F800000u) lf++;
        else lo++;
    }
    atomicAdd(&s_other, lo); atomicAdd(&s_f1, lf); atomicAdd(&s_i1, li);
    __syncthreads();
    if (s_other > 64) return 0;
    return (s_f1 >= s_i1) ? 2 : 1;
}

// ---------------------------------------------------------------------------
// MEGA kernel: split-K gemm1 (256 CTAs) + remaining prep work
// ---------------------------------------------------------------------------
#define MEGA_GEMM 256
#define AUX_RED   79
#define AUX_W2    256
#define AUX_WLR1  256
#define AUX_WLR2  256
#define AUX_BLR   8
#define AUX_W4    10000
#define AUX_W6    10000
#define MEGA_BLOCKS (MEGA_GEMM + AUX_RED + AUX_W2 + AUX_WLR1 + AUX_WLR2 + \
                     AUX_BLR + AUX_W4 + AUX_W6)

__global__ __launch_bounds__(256, 2)
void mega_kernel(const __half* __restrict__ noisyh,
                 const __half* __restrict__ W1c, float* __restrict__ psum,
                 const float* __restrict__ part, float* __restrict__ out_pop,
                 const float* __restrict__ enc_w2, __half* __restrict__ W2c,
                 const float* __restrict__ lk_w1, const float* __restrict__ rc_w1,
                 __half* __restrict__ Wlr,
                 const float* __restrict__ lk_b1, const float* __restrict__ rc_b1,
                 float* __restrict__ blr,
                 const float* __restrict__ lk_w2, __half* __restrict__ W4c,
                 const float* __restrict__ rc_w2, __half* __restrict__ W6c) {
    extern __shared__ __align__(128) char smem[];
    int bid = blockIdx.x;
    if (bid < MEGA_GEMM) {
        int z = bid >> 7;            // K split 0/1
        int bx = bid & 15;           // m tile
        int by = (bid >> 4) & 7;     // n tile
        const __half* A = noisyh + (size_t)z * KHALF;
        const __half* B = W1c + (size_t)z * KHALF * HID;
        float* C = psum + (size_t)z * BATCH * HID;
        gemm_body<ACT_NONE, false, false, true>(
            A, B, nullptr, C, BATCH, HID, KHALF, KPAD, HID, bx, by, smem);
        return;
    }
    int aux = bid - MEGA_GEMM;
    if (aux < AUX_RED) { aux_popular_reduce(aux, part, out_pop); return; }
    aux -= AUX_RED;
    if (aux < AUX_W2) {
        aux_convert_pad(aux, enc_w2, W2c, (long)HID * EMB, (long)HID * EMB / 8);
        return;
    }
    aux -= AUX_W2;
    if (aux < AUX_WLR1) {
        aux_convert_cols(aux, lk_w1, Wlr, HID, 2 * HID, 0, EMB * HID / 8);
        return;
    }
    aux -= AUX_WLR1;
    if (aux < AUX_WLR2) {
        aux_convert_cols(aux, rc_w1, Wlr, HID, 2 * HID, HID, EMB * HID / 8);
        return;
    }
    aux -= AUX_WLR2;
    if (aux < AUX_BLR) { aux_concat2(aux, lk_b1, rc_b1, blr, HID); return; }
    aux -= AUX_BLR;
    if (aux < AUX_W4) {
        aux_convert_pad(aux, lk_w2, W4c, (long)HID * NITEMS,
                        (long)HID * NITEMS / 8);
        return;
    }
    aux -= AUX_W4;
    aux_convert_pad(aux, rc_w2, W6c, (long)HID * NITEMS,
                    (long)HID * NITEMS / 8);
}

// ---------------------------------------------------------------------------
// Merged prep: premask+popular partials (w/ per-block mask probe) + W1 convert
// ---------------------------------------------------------------------------
#define PREM_X 79                       // ceil(KPAD/256)
#define PREM_BLOCKS (PREM_X * 16)       // 1264
#define W1_BLOCKS ((KPAD * HID / 8) / 256)  // 10048
#define PREP_BLOCKS (PREM_BLOCKS + W1_BLOCKS)

__global__ void prep_kernel(const float* __restrict__ likes,
                            const void* __restrict__ mask,
                            __half* __restrict__ noisy,
                            float* __restrict__ part,
                            const float* __restrict__ enc_w1,
                            __half* __restrict__ W1c) {
    int bid = blockIdx.x;
    if (bid >= PREM_BLOCKS) {
        aux_convert_pad(bid - PREM_BLOCKS, enc_w1, W1c,
                        (long)NITEMS * HID, (long)KPAD * HID / 8);
        return;
    }
    const int mode = probe_mode_block((const unsigned int*)mask);
    const int col = (bid % PREM_X) * 256 + threadIdx.x;
    if (col >= KPAD) return;
    const int r0 = (bid / PREM_X) * 128;

    if (col >= NITEMS) {  // padding region: zero noisy, no popular
        const __half hz = __float2half_rn(0.f);
        for (int r = 0; r < 128; r++)
            noisy[(size_t)(r0 + r) * KPAD + col] = hz;
        return;
    }

    const unsigned char* m8 = (const unsigned char*)mask;
    const int*           mi = (const int*)mask;
    const float*         mf = (const float*)mask;

    float sum = 0.f;
    #pragma unroll 4
    for (int r = 0; r < 128; r++) {
        size_t e = (size_t)(r0 + r) * NITEMS + col;
        float v = likes[e];
        sum += v;
        bool drop;
        if (mode == 0)      drop = (m8[e] != 0);
        else if (mode == 1) drop = (mi[e] != 0);
        else                drop = (mf[e] != 0.f);
        noisy[(size_t)(r0 + r) * KPAD + col] = __float2half_rn(drop ? 0.f : v);
    }
    part[(bid / PREM_X) * NITEMS + col] = sum;
}

// combine split-K partials: Hh = fp16(relu(p0 + p1 + bias))
__global__ void combine_splitk_kernel(const float* __restrict__ p,
                                      const float* __restrict__ bias,
                                      __half* __restrict__ out) {
    const size_t MN = (size_t)BATCH * HID;
    size_t e = ((size_t)blockIdx.x * 256 + threadIdx.x) * 4;
    if (e >= MN) return;
    int col = (int)(e & (HID - 1));
    float4 a = *reinterpret_cast<const float4*>(p + e);
    float4 b = *reinterpret_cast<const float4*>(p + MN + e);
    float4 bb = *reinterpret_cast<const float4*>(bias + col);
    float x0 = fmaxf(a.x + b.x + bb.x, 0.f);
    float x1 = fmaxf(a.y + b.y + bb.y, 0.f);
    float x2 = fmaxf(a.z + b.z + bb.z, 0.f);
    float x3 = fmaxf(a.w + b.w + bb.w, 0.f);
    __half2* dst = reinterpret_cast<__half2*>(out + e);
    dst[0] = __floats2half2_rn(x0, x1);
    dst[1] = __floats2half2_rn(x2, x3);
}

// per-row l2 normalize; emit fp16 normalized AND fp16 copy of E
__global__ void norm_half_kernel(const float* __restrict__ E,
                                 __half* __restrict__ Nrmh,
                                 __half* __restrict__ Eh) {
    int row = blockIdx.x;
    int t = threadIdx.x;
    float4 v = reinterpret_cast<const float4*>(E + (size_t)row * EMB)[t];
    float ss = v.x * v.x + v.y * v.y + v.z * v.z + v.w * v.w;
    #pragma unroll
    for (int o = 16; o > 0; o >>= 1)
        ss += __shfl_xor_sync(0xFFFFFFFFu, ss, o);
    __shared__ float ws[4];
    if ((t & 31) == 0) ws[t >> 5] = ss;
    __syncthreads();
    float tot = ws[0] + ws[1] + ws[2] + ws[3];
    float inv = rsqrtf(fmaxf(tot, 1e-12f));
    __half2* eh = reinterpret_cast<__half2*>(Eh + (size_t)row * EMB + t * 4);
    eh[0] = __floats2half2_rn(v.x, v.y);
    eh[1] = __floats2half2_rn(v.z, v.w);
    __half2* nh = reinterpret_cast<__half2*>(Nrmh + (size_t)row * EMB + t * 4);
    nh[0] = __floats2half2_rn(v.x * inv, v.y * inv);
    nh[1] = __floats2half2_rn(v.z * inv, v.w * inv);
}

#define NO_DUAL nullptr, nullptr, nullptr, nullptr, 0x40000000

// ---------------------------------------------------------------------------
// Launch
// ---------------------------------------------------------------------------
extern "C" void kernel_launch(void* const* d_in, const int* in_sizes, int n_in,
                              void* d_out, int out_size) {
    const float* likes  = (const float*)d_in[1];
    const void*  nmask  = d_in[2];
    const float* enc_w1 = (const float*)d_in[3];
    const float* enc_b1 = (const float*)d_in[4];
    const float* enc_w2 = (const float*)d_in[5];
    const float* enc_b2 = (const float*)d_in[6];
    const float* lk_w1  = (const float*)d_in[7];
    const float* lk_b1  = (const float*)d_in[8];
    const float* lk_w2  = (const float*)d_in[9];
    const float* lk_b2  = (const float*)d_in[10];
    const float* rc_w1  = (const float*)d_in[11];
    const float* rc_b1  = (const float*)d_in[12];
    const float* rc_w2  = (const float*)d_in[13];
    const float* rc_b2  = (const float*)d_in[14];

    float* out       = (float*)d_out;
    float* out_likes = out;
    float* out_sim   = out_likes + (size_t)BATCH * NITEMS;
    float* out_rec   = out_sim + (size_t)BATCH * BATCH;
    float* out_pop   = out_rec + (size_t)BATCH * NITEMS;

    __half *noisyh, *W1c, *W2c, *Wlr, *W4c, *W6c, *Hh, *Hh2, *Eh, *Nrmh;
    float *E, *part, *blr, *psum;
    cudaGetSymbolAddress((void**)&noisyh, g_noisyh);
    cudaGetSymbolAddress((void**)&W1c, g_W1c);
    cudaGetSymbolAddress((void**)&W2c, g_W2c);
    cudaGetSymbolAddress((void**)&Wlr, g_Wlr);
    cudaGetSymbolAddress((void**)&W4c, g_W4c);
    cudaGetSymbolAddress((void**)&W6c, g_W6c);
    cudaGetSymbolAddress((void**)&blr, g_blr);
    cudaGetSymbolAddress((void**)&psum, g_psum);
    cudaGetSymbolAddress((void**)&Hh, g_Hh);
    cudaGetSymbolAddress((void**)&Hh2, g_Hh2);
    cudaGetSymbolAddress((void**)&E, g_E);
    cudaGetSymbolAddress((void**)&Eh, g_Eh);
    cudaGetSymbolAddress((void**)&Nrmh, g_Nrmh);
    cudaGetSymbolAddress((void**)&part, g_part);

    const int smem = NSTAGE * SSZ;      // 96KB (BN=128 body)
    const int smem64 = NSTAGE * SSZ64;  // 72KB (BN=64 body)
    cudaFuncSetAttribute(mega_kernel,
                         cudaFuncAttributeMaxDynamicSharedMemorySize, smem);
    cudaFuncSetAttribute(simhid_kernel,
                         cudaFuncAttributeMaxDynamicSharedMemorySize, smem);
    cudaFuncSetAttribute(gemm2_kernel,
                         cudaFuncAttributeMaxDynamicSharedMemorySize, smem64);
    cudaFuncSetAttribute(hmma_gemm<ACT_SIG, true, false, true>,
                         cudaFuncAttributeMaxDynamicSharedMemorySize, smem);

    // 1: merged prep -- denoise+popular partials (self-probing) + W1 convert
    prep_kernel<<<PREP_BLOCKS, 256>>>(likes, nmask, noisyh, part, enc_w1, W1c);
    // 2: MEGA -- split-K gemm1 + all remaining independent prep work
    mega_kernel<<<MEGA_BLOCKS, 256, smem>>>(
        noisyh, W1c, psum, part, out_pop,
        enc_w2, W2c, lk_w1, rc_w1, Wlr, lk_b1, rc_b1, blr,
        lk_w2, W4c, rc_w2, W6c);
    // 3: combine partials -> Hh = fp16(relu(p0+p1+b1))
    combine_splitk_kernel<<<(int)(((size_t)BATCH * HID / 4 + 255) / 256), 256>>>(
        psum, enc_b1, Hh);

    // 4: encoder layer 2 (128x64 tiles -> 128 CTAs)
    gemm2_kernel<<<dim3(BATCH / 128, EMB / 64), 256, smem64>>>(
        Hh, W2c, enc_b2, E);
    // 5: norm
    norm_half_kernel<<<BATCH, 128>>>(E, Nrmh, Eh);

    // 6: merged sim (upper triangle + mirror) + head-hidden (392 CTAs)
    simhid_kernel<<<392, 256, smem>>>(Nrmh, out_sim, Eh, Wlr, blr, Hh2);

    // 7: BOTH head outputs in ONE launch (wave merge)
    const int nTiles = (NITEMS + 127) / 128;  // 157
    hmma_gemm<ACT_SIG, true, false, true>
        <<<dim3(BATCH / 128, 2 * nTiles), 256, smem>>>(
        Hh2, W4c, lk_b2, out_likes, BATCH, NITEMS, HID, 2 * HID, NITEMS,
        Hh2 + HID, W6c, rc_b2, out_rec, nTiles);
}

// round 17
// speedup vs baseline: 1.2720x; 1.0410x over previous
#include <cuda_runtime.h>
#include <cuda_fp16.h>
#include <cstdint>

// Problem constants
#define BATCH  2048
#define NITEMS 20000
#define KPAD   20096   // NITEMS padded to 2 x 10048 (157 x 64 per K-split)
#define KHALF  10048
#define EMB    512
#define HID    1024    // 2*D

// ---------------------------------------------------------------------------
// Scratch (no allocations -> __device__ globals)
// ---------------------------------------------------------------------------
__device__ __half g_noisyh[(size_t)BATCH * KPAD];    // masked likes fp16, padded
__device__ __half g_W1c[(size_t)KPAD * HID];         // enc_w1 fp16 [20096][1024]
__device__ __half g_W2c[(size_t)HID * EMB];          // enc_w2 fp16 [1024][512]
__device__ __half g_Wlr[(size_t)EMB * (2 * HID)];    // [512][2048] = lk_w1 ++ rc_w1
__device__ __half g_W4c[(size_t)HID * NITEMS];       // lk_w2 fp16 [1024][20000]
__device__ __half g_W6c[(size_t)HID * NITEMS];       // rc_w2 fp16 [1024][20000]
__device__ float  g_blr[2 * HID];                    // lk_b1 ++ rc_b1
__device__ float  g_psum[2 * (size_t)BATCH * HID];   // split-K partials (f32)
__device__ __half g_Hh[(size_t)BATCH * HID];         // encoder hidden fp16
__device__ __half g_Hh2[(size_t)BATCH * 2 * HID];    // fused head hiddens fp16
__device__ float  g_E[(size_t)BATCH * EMB];          // embed f32
__device__ __half g_Eh[(size_t)BATCH * EMB];         // embed fp16
__device__ __half g_Nrmh[(size_t)BATCH * EMB];       // normalized fp16
__device__ float  g_part[16 * NITEMS];

// ---------------------------------------------------------------------------
// PTX helpers (arch-generic sm_80-era instructions)
// ---------------------------------------------------------------------------
__device__ __forceinline__ uint32_t smem_u32(const void* p) {
    uint32_t a;
    asm("{ .reg .u64 t; cvta.to.shared.u64 t, %1; cvt.u32.u64 %0, t; }"
        : "=r"(a) : "l"(p));
    return a;
}
__device__ __forceinline__ void cp16(uint32_t dst, const void* src, int sz) {
    asm volatile("cp.async.cg.shared.global [%0], [%1], 16, %2;"
        :: "r"(dst), "l"(src), "r"(sz));
}
#define CP_COMMIT() asm volatile("cp.async.commit_group;" ::: "memory")
#define CP_WAIT(n)  asm volatile("cp.async.wait_group %0;" :: "n"(n) : "memory")

#define LDSM_X4(r, addr) \
    asm volatile("ldmatrix.sync.aligned.m8n8.x4.shared.b16 {%0,%1,%2,%3}, [%4];" \
        : "=r"((r)[0]), "=r"((r)[1]), "=r"((r)[2]), "=r"((r)[3]) : "r"(addr))

#define LDSM_X4_T(r, addr) \
    asm volatile("ldmatrix.sync.aligned.m8n8.x4.trans.shared.b16 {%0,%1,%2,%3}, [%4];" \
        : "=r"((r)[0]), "=r"((r)[1]), "=r"((r)[2]), "=r"((r)[3]) : "r"(addr))

__device__ __forceinline__ void mma16816(float* d, const uint32_t* a,
                                         uint32_t b0, uint32_t b1) {
    asm volatile(
        "mma.sync.aligned.m16n8k16.row.col.f32.f16.f16.f32 "
        "{%0,%1,%2,%3}, {%4,%5,%6,%7}, {%8,%9}, {%0,%1,%2,%3};"
        : "+f"(d[0]), "+f"(d[1]), "+f"(d[2]), "+f"(d[3])
        : "r"(a[0]), "r"(a[1]), "r"(a[2]), "r"(a[3]), "r"(b0), "r"(b1));
}

enum { ACT_RELU = 0, ACT_SIG = 1, ACT_NEG = 2, ACT_NONE = 3 };
#define BK 64
#define NSTAGE 3
#define ASZ 16384                 // A: 128 rows * 128B ; B(trans): 64 rows * 256B
#define SSZ 32768                 // A + B per stage (BN=128 body)

// ---------------------------------------------------------------------------
// GEMM body, CTA tile 128x128, 8 warps of 64x32, occ 2.
// Mainloop unrolled by NSTAGE with compile-time stage indices (no modulo /
// dynamic stage addressing in the hot path); small dynamic remainder loop.
// Single __syncthreads per K-chunk; 3 stages, prefetch distance 2.
// MIRROR (sim only): also write the transposed tile (symmetric output).
// ---------------------------------------------------------------------------
template<int ACT, bool HAS_BIAS, bool OUT_HALF, bool TRANSB, bool MIRROR = false>
__device__ __forceinline__ void gemm_body(
    const __half* __restrict__ A, const __half* __restrict__ Bt,
    const float* __restrict__ bias, void* __restrict__ Cout,
    int M, int N, int K, int lda, int ldb, int bx, int by, char* smem,
    bool do_mirror = false) {
    const uint32_t sbase = smem_u32(smem);

    const int tid = threadIdx.x;
    const int lane = tid & 31, wid = tid >> 5;
    const int wm = (wid & 1) * 64;
    const int wn = (wid >> 1) * 32;
    const int m0 = bx * 128;
    const int n0 = by * 128;
    const int nch = K / BK;

    float acc[4][4][4];
    #pragma unroll
    for (int i = 0; i < 4; i++)
        #pragma unroll
        for (int j = 0; j < 4; j++)
            #pragma unroll
            for (int q = 0; q < 4; q++) acc[i][j][q] = 0.f;

    auto load_stage = [&](int ch, int st) {
        const int k0 = ch * BK;
        const uint32_t sA = sbase + st * SSZ;
        const uint32_t sB = sA + ASZ;
        #pragma unroll
        for (int u = 0; u < 4; u++) {
            int idx = tid + u * 256;
            int r = idx >> 3, c = idx & 7;
            const __half* src = A + (size_t)(m0 + r) * lda + k0 + c * 8;
            cp16(sA + r * 128 + ((c ^ (r & 7)) << 4), src, 16);
        }
        if constexpr (!TRANSB) {
            #pragma unroll
            for (int u = 0; u < 4; u++) {
                int idx = tid + u * 256;
                int r = idx >> 3, c = idx & 7;
                int n = n0 + r;
                const __half* src = Bt + (size_t)n * ldb + k0 + c * 8;
                cp16(sB + r * 128 + ((c ^ (r & 7)) << 4), src, (n < N) ? 16 : 0);
            }
        } else {
            // B tile [BK=64 k-rows][128 n], 256B per k-row, per-128B-half swizzle
            #pragma unroll
            for (int u = 0; u < 4; u++) {
                int idx = tid + u * 256;
                int k = idx >> 4, c = idx & 15;
                const __half* src = Bt + (size_t)(k0 + k) * ldb + n0 + c * 8;
                uint32_t dst = sB + k * 256 + ((c >> 3) << 7)
                             + (((c & 7) ^ (k & 7)) << 4);
                cp16(dst, src, (n0 + c * 8 + 8 <= N) ? 16 : 0);
            }
        }
        CP_COMMIT();
    };

    const int aRow = wm + (lane & 15);
    const int aKsel = lane >> 4;
    const int swz = lane & 7;
    const int bRow = wn + ((lane >> 4) << 3) + (lane & 7);
    const int bKsel = (lane >> 3) & 1;
    const int kLane = ((lane >> 3) & 1) * 8 + (lane & 7);
    int bOffT0 = 0, bOffT1 = 0;
    {
        int n0l = wn + ((lane >> 4) << 3);
        int c0 = n0l >> 3, c1 = (n0l + 16) >> 3;
        bOffT0 = ((c0 >> 3) << 7) + (((c0 & 7) ^ (lane & 7)) << 4);
        bOffT1 = ((c1 >> 3) << 7) + (((c1 & 7) ^ (lane & 7)) << 4);
    }

    // one iteration: wait stage stC, prefetch chunk i+2 into stage stL,
    // compute chunk i from stage stC. stC/stL become compile-time constants
    // in the unrolled main loop.
    auto iter = [&](int i, int stC, int stL) {
        CP_WAIT(1);
        __syncthreads();
        const int j = i + 2;
        if (j < nch) load_stage(j, stL);
        else         CP_COMMIT();

        const uint32_t sA = sbase + stC * SSZ;
        const uint32_t sB = sA + ASZ;
        #pragma unroll
        for (int kk = 0; kk < 4; kk++) {
            uint32_t a[4][4], b[2][4];
            const uint32_t aByte = ((2 * kk + aKsel) ^ swz) << 4;
            #pragma unroll
            for (int mf = 0; mf < 4; mf++)
                LDSM_X4(a[mf], sA + (aRow + 16 * mf) * 128 + aByte);
            if constexpr (!TRANSB) {
                const uint32_t bByte = ((2 * kk + bKsel) ^ swz) << 4;
                #pragma unroll
                for (int nf2 = 0; nf2 < 2; nf2++)
                    LDSM_X4(b[nf2], sB + (bRow + 16 * nf2) * 128 + bByte);
            } else {
                const uint32_t rowB = sB + (kk * 16 + kLane) * 256;
                LDSM_X4_T(b[0], rowB + bOffT0);
                LDSM_X4_T(b[1], rowB + bOffT1);
            }
            #pragma unroll
            for (int mf = 0; mf < 4; mf++)
                #pragma unroll
                for (int nf = 0; nf < 4; nf++)
                    mma16816(acc[mf][nf], a[mf],
                             b[nf >> 1][(nf & 1) * 2],
                             b[nf >> 1][(nf & 1) * 2 + 1]);
        }
    };

    load_stage(0, 0);
    load_stage(1, 1);

    const int full = (nch / 3) * 3;
    for (int i = 0; i < full; i += 3) {
        iter(i,     0, 2);
        iter(i + 1, 1, 0);
        iter(i + 2, 2, 1);
    }
    for (int i = full; i < nch; i++) {   // 0..2 leftover chunks
        int stC = i - full;              // full % 3 == 0 -> i % 3
        int stL = stC + 2 >= 3 ? stC - 1 : stC + 2;
        iter(i, stC, stL);
    }

    #pragma unroll
    for (int mf = 0; mf < 4; mf++) {
        const int row = m0 + wm + mf * 16 + (lane >> 2);
        #pragma unroll
        for (int nf = 0; nf < 4; nf++) {
            const int col = n0 + wn + nf * 8 + 2 * (lane & 3);
            if (col >= N) continue;
            float2 lo = make_float2(acc[mf][nf][0], acc[mf][nf][1]);
            float2 hi = make_float2(acc[mf][nf][2], acc[mf][nf][3]);
            if (HAS_BIAS) {
                float2 bb = *reinterpret_cast<const float2*>(bias + col);
                lo.x += bb.x; lo.y += bb.y;
                hi.x += bb.x; hi.y += bb.y;
            }
            if (ACT == ACT_RELU) {
                lo.x = fmaxf(lo.x, 0.f); lo.y = fmaxf(lo.y, 0.f);
                hi.x = fmaxf(hi.x, 0.f); hi.y = fmaxf(hi.y, 0.f);
            } else if (ACT == ACT_SIG) {
                lo.x = __fdividef(1.f, 1.f + __expf(-lo.x));
                lo.y = __fdividef(1.f, 1.f + __expf(-lo.y));
                hi.x = __fdividef(1.f, 1.f + __expf(-hi.x));
                hi.y = __fdividef(1.f, 1.f + __expf(-hi.y));
            } else if (ACT == ACT_NEG) {
                lo.x = -lo.x; lo.y = -lo.y;
                hi.x = -hi.x; hi.y = -hi.y;
            }
            if (OUT_HALF) {
                __half* C = (__half*)Cout;
                *reinterpret_cast<__half2*>(C + (size_t)row * N + col) =
                    __floats2half2_rn(lo.x, lo.y);
                *reinterpret_cast<__half2*>(C + (size_t)(row + 8) * N + col) =
                    __floats2half2_rn(hi.x, hi.y);
            } else {
                float* C = (float*)Cout;
                *reinterpret_cast<float2*>(C + (size_t)row * N + col) = lo;
                *reinterpret_cast<float2*>(C + (size_t)(row + 8) * N + col) = hi;
                if (MIRROR && do_mirror) {
                    // transposed writes: same values, bitwise-identical math
                    C[(size_t)col * N + row]           = lo.x;
                    C[(size_t)(col + 1) * N + row]     = lo.y;
                    C[(size_t)col * N + row + 8]       = hi.x;
                    C[(size_t)(col + 1) * N + row + 8] = hi.y;
                }
            }
        }
    }
}

// ---------------------------------------------------------------------------
// GEMM body, CTA tile 128x64, TRANSB only (R14-proven geometry). Used for the
// small encoder-layer-2 GEMM to double its CTA parallelism.
// ---------------------------------------------------------------------------
#define BSZ64 8192
#define SSZ64 (ASZ + BSZ64)

template<int ACT, bool HAS_BIAS, bool OUT_HALF>
__device__ __forceinline__ void gemm_body64(
    const __half* __restrict__ A, const __half* __restrict__ Bt,
    const float* __restrict__ bias, void* __restrict__ Cout,
    int M, int N, int K, int lda, int ldb, int bx, int by, char* smem) {
    const uint32_t sbase = smem_u32(smem);

    const int tid = threadIdx.x;
    const int lane = tid & 31, wid = tid >> 5;
    const int wm = (wid & 3) * 32;        // 4 m-warps
    const int wn = (wid >> 2) * 32;       // 2 n-warps
    const int m0 = bx * 128;
    const int n0 = by * 64;
    const int nch = K / BK;

    float acc[2][4][4];
    #pragma unroll
    for (int i = 0; i < 2; i++)
        #pragma unroll
        for (int j = 0; j < 4; j++)
            #pragma unroll
            for (int q = 0; q < 4; q++) acc[i][j][q] = 0.f;

    auto load_stage = [&](int ch, int st) {
        const int k0 = ch * BK;
        const uint32_t sA = sbase + st * SSZ64;
        const uint32_t sB = sA + ASZ;
        #pragma unroll
        for (int u = 0; u < 4; u++) {
            int idx = tid + u * 256;
            int r = idx >> 3, c = idx & 7;
            const __half* src = A + (size_t)(m0 + r) * lda + k0 + c * 8;
            cp16(sA + r * 128 + ((c ^ (r & 7)) << 4), src, 16);
        }
        #pragma unroll
        for (int u = 0; u < 2; u++) {
            int idx = tid + u * 256;
            int k = idx >> 3, c = idx & 7;
            const __half* src = Bt + (size_t)(k0 + k) * ldb + n0 + c * 8;
            uint32_t dst = sB + k * 128 + ((c ^ (k & 7)) << 4);
            cp16(dst, src, (n0 + c * 8 + 8 <= N) ? 16 : 0);
        }
        CP_COMMIT();
    };

    const int aRow = wm + (lane & 15);
    const int aKsel = lane >> 4;
    const int swz = lane & 7;
    const int kLane = ((lane >> 3) & 1) * 8 + (lane & 7);
    int bOffT0 = 0, bOffT1 = 0;
    {
        int n0l = wn + ((lane >> 4) << 3);
        int c0 = n0l >> 3, c1 = (n0l + 16) >> 3;
        bOffT0 = ((c0 ^ (lane & 7)) << 4);
        bOffT1 = ((c1 ^ (lane & 7)) << 4);
    }

    load_stage(0, 0);
    load_stage(1, 1);

    for (int i = 0; i < nch; i++) {
        CP_WAIT(1);
        __syncthreads();
        const int j = i + 2;
        if (j < nch) load_stage(j, j % NSTAGE);
        else         CP_COMMIT();

        const uint32_t sA = sbase + (i % NSTAGE) * SSZ64;
        const uint32_t sB = sA + ASZ;
        #pragma unroll
        for (int kk = 0; kk < 4; kk++) {
            uint32_t a[2][4], b[2][4];
            const uint32_t aByte = ((2 * kk + aKsel) ^ swz) << 4;
            #pragma unroll
            for (int mf = 0; mf < 2; mf++)
                LDSM_X4(a[mf], sA + (aRow + 16 * mf) * 128 + aByte);
            const uint32_t rowB = sB + (kk * 16 + kLane) * 128;
            LDSM_X4_T(b[0], rowB + bOffT0);
            LDSM_X4_T(b[1], rowB + bOffT1);
            #pragma unroll
            for (int mf = 0; mf < 2; mf++)
                #pragma unroll
                for (int nf = 0; nf < 4; nf++)
                    mma16816(acc[mf][nf], a[mf],
                             b[nf >> 1][(nf & 1) * 2],
                             b[nf >> 1][(nf & 1) * 2 + 1]);
        }
    }

    #pragma unroll
    for (int mf = 0; mf < 2; mf++) {
        const int row = m0 + wm + mf * 16 + (lane >> 2);
        #pragma unroll
        for (int nf = 0; nf < 4; nf++) {
            const int col = n0 + wn + nf * 8 + 2 * (lane & 3);
            if (col >= N) continue;
            float2 lo = make_float2(acc[mf][nf][0], acc[mf][nf][1]);
            float2 hi = make_float2(acc[mf][nf][2], acc[mf][nf][3]);
            if (HAS_BIAS) {
                float2 bb = *reinterpret_cast<const float2*>(bias + col);
                lo.x += bb.x; lo.y += bb.y;
                hi.x += bb.x; hi.y += bb.y;
            }
            if (ACT == ACT_RELU) {
                lo.x = fmaxf(lo.x, 0.f); lo.y = fmaxf(lo.y, 0.f);
                hi.x = fmaxf(hi.x, 0.f); hi.y = fmaxf(hi.y, 0.f);
            }
            if (OUT_HALF) {
                __half* C = (__half*)Cout;
                *reinterpret_cast<__half2*>(C + (size_t)row * N + col) =
                    __floats2half2_rn(lo.x, lo.y);
                *reinterpret_cast<__half2*>(C + (size_t)(row + 8) * N + col) =
                    __floats2half2_rn(hi.x, hi.y);
            } else {
                float* C = (float*)Cout;
                *reinterpret_cast<float2*>(C + (size_t)row * N + col) = lo;
                *reinterpret_cast<float2*>(C + (size_t)(row + 8) * N + col) = hi;
            }
        }
    }
}

// ---------------------------------------------------------------------------
// Standalone GEMM kernels
// ---------------------------------------------------------------------------
template<int ACT, bool HAS_BIAS, bool OUT_HALF, bool TRANSB>
__global__ __launch_bounds__(256, 2)
void hmma_gemm(const __half* __restrict__ Ap, const __half* __restrict__ Bp,
               const float* __restrict__ biasp, void* __restrict__ Coutp,
               int M, int N, int K, int lda, int ldb,
               const __half* A2, const __half* B2,
               const float* bias2, void* Cout2, int nSplit) {
    extern __shared__ __align__(128) char smem[];
    const __half* A   = Ap;
    const __half* Bt  = Bp;
    const float* bias = biasp;
    void* Cout        = Coutp;
    int by = blockIdx.y;
    if (by >= nSplit) {
        by -= nSplit;
        A = A2; Bt = B2; bias = bias2; Cout = Cout2;
    }
    gemm_body<ACT, HAS_BIAS, OUT_HALF, TRANSB>(
        A, Bt, bias, Cout, M, N, K, lda, ldb, blockIdx.x, by, smem);
}

// encoder layer 2 with 128x64 tiles (128 CTAs)
__global__ __launch_bounds__(256, 2)
void gemm2_kernel(const __half* __restrict__ Hh, const __half* __restrict__ W2c,
                  const float* __restrict__ enc_b2, float* __restrict__ E) {
    extern __shared__ __align__(128) char smem[];
    gemm_body64<ACT_RELU, true, false>(
        Hh, W2c, enc_b2, E, BATCH, EMB, HID, HID, EMB,
        blockIdx.x, blockIdx.y, smem);
}

// merged sim (upper triangle only, mirrored) + head-hidden.
__global__ __launch_bounds__(256, 2)
void simhid_kernel(const __half* __restrict__ Nrmh, float* __restrict__ out_sim,
                   const __half* __restrict__ Eh, const __half* __restrict__ Wlr,
                   const float* __restrict__ blr, __half* __restrict__ Hh2) {
    extern __shared__ __align__(128) char smem[];
    int bid = blockIdx.x;
    if (bid < 136) {
        // map bid -> upper-triangle pair (i, j), i <= j, 16x16 tile grid
        int i = 0, t = bid;
        while (t >= 16 - i) { t -= 16 - i; i++; }
        int j = i + t;
        gemm_body<ACT_NEG, false, false, false, true>(
            Nrmh, Nrmh, nullptr, out_sim, BATCH, BATCH, EMB, EMB, EMB,
            i, j, smem, i != j);
    } else {
        bid -= 136;
        gemm_body<ACT_RELU, true, true, true>(
            Eh, Wlr, blr, Hh2, BATCH, 2 * HID, EMB, EMB, 2 * HID,
            bid & 15, bid >> 4, smem);
    }
}

// ---------------------------------------------------------------------------
// Aux device helpers
// ---------------------------------------------------------------------------
__device__ __forceinline__ void aux_popular_reduce(
    int b, const float* __restrict__ part, float* __restrict__ out_pop) {
    int i = b * 256 + threadIdx.x;
    if (i >= NITEMS) return;
    float s = 0.f;
    #pragma unroll
    for (int c = 0; c < 16; c++) s += part[c * NITEMS + i];
    out_pop[i] = s * (1.0f / (float)BATCH);
}

__device__ __forceinline__ void aux_convert_pad(
    int b, const float* __restrict__ in, __half* __restrict__ out,
    long validElems, long total8) {
    long i = (long)b * 256 + threadIdx.x;
    if (i >= total8) return;
    long e = i * 8;
    __half2 h[4];
    if (e + 8 <= validElems) {
        float4 a = *reinterpret_cast<const float4*>(in + e);
        float4 bb = *reinterpret_cast<const float4*>(in + e + 4);
        h[0] = __floats2half2_rn(a.x, a.y);
        h[1] = __floats2half2_rn(a.z, a.w);
        h[2] = __floats2half2_rn(bb.x, bb.y);
        h[3] = __floats2half2_rn(bb.z, bb.w);
    } else {
        h[0] = h[1] = h[2] = h[3] = __floats2half2_rn(0.f, 0.f);
    }
    __half2* dst = reinterpret_cast<__half2*>(out + e);
    dst[0] = h[0]; dst[1] = h[1]; dst[2] = h[2]; dst[3] = h[3];
}

__device__ __forceinline__ void aux_convert_cols(
    int b, const float* __restrict__ in, __half* __restrict__ out,
    int C, int ldo, int colOff, int total8) {
    int i = b * 256 + threadIdx.x;
    if (i >= total8) return;
    long e = (long)i * 8;
    int k = (int)(e / C);
    int c = (int)(e - (long)k * C);
    float4 a = *reinterpret_cast<const float4*>(in + e);
    float4 bb = *reinterpret_cast<const float4*>(in + e + 4);
    __half2* dst = reinterpret_cast<__half2*>(out + (size_t)k * ldo + colOff + c);
    dst[0] = __floats2half2_rn(a.x, a.y);
    dst[1] = __floats2half2_rn(a.z, a.w);
    dst[2] = __floats2half2_rn(bb.x, bb.y);
    dst[3] = __floats2half2_rn(bb.z, bb.w);
}

__device__ __forceinline__ void aux_concat2(
    int b, const float* __restrict__ a, const float* __restrict__ bsrc,
    float* __restrict__ o, int n) {
    int i = b * 256 + threadIdx.x;
    if (i < n) o[i] = a[i];
    else if (i < 2 * n) o[i] = bsrc[i - n];
}

// Per-block mask-dtype probe (first 2048 words; L2-cached after first block)
__device__ __forceinline__ int probe_mode_block(const unsigned int* w) {
    __shared__ int s_other, s_f1, s_i1;
    if (threadIdx.x == 0) { s_other = 0; s_f1 = 0; s_i1 = 0; }
    __syncthreads();
    int lo = 0, lf = 0, li = 0;
    for (int i = threadIdx.x; i < 2048; i += blockDim.x) {
        unsigned v = w[i];
        if (v == 0u) continue;
        else if (v == 1u) li++;
        else if (v == 0x3F800000u) lf++;
        else lo++;
    }
    atomicAdd(&s_other, lo); atomicAdd(&s_f1, lf); atomicAdd(&s_i1, li);
    __syncthreads();
    if (s_other > 64) return 0;
    return (s_f1 >= s_i1) ? 2 : 1;
}

// ---------------------------------------------------------------------------
// MEGA kernel: split-K gemm1 (256 CTAs) + remaining prep work
// ---------------------------------------------------------------------------
#define MEGA_GEMM 256
#define AUX_RED   79
#define AUX_W2    256
#define AUX_WLR1  256
#define AUX_WLR2  256
#define AUX_BLR   8
#define AUX_W4    10000
#define AUX_W6    10000
#define MEGA_BLOCKS (MEGA_GEMM + AUX_RED + AUX_W2 + AUX_WLR1 + AUX_WLR2 + \
                     AUX_BLR + AUX_W4 + AUX_W6)

__global__ __launch_bounds__(256, 2)
void mega_kernel(const __half* __restrict__ noisyh,
                 const __half* __restrict__ W1c, float* __restrict__ psum,
                 const float* __restrict__ part, float* __restrict__ out_pop,
                 const float* __restrict__ enc_w2, __half* __restrict__ W2c,
                 const float* __restrict__ lk_w1, const float* __restrict__ rc_w1,
                 __half* __restrict__ Wlr,
                 const float* __restrict__ lk_b1, const float* __restrict__ rc_b1,
                 float* __restrict__ blr,
                 const float* __restrict__ lk_w2, __half* __restrict__ W4c,
                 const float* __restrict__ rc_w2, __half* __restrict__ W6c) {
    extern __shared__ __align__(128) char smem[];
    int bid = blockIdx.x;
    if (bid < MEGA_GEMM) {
        int z = bid >> 7;            // K split 0/1
        int bx = bid & 15;           // m tile
        int by = (bid >> 4) & 7;     // n tile
        const __half* A = noisyh + (size_t)z * KHALF;
        const __half* B = W1c + (size_t)z * KHALF * HID;
        float* C = psum + (size_t)z * BATCH * HID;
        gemm_body<ACT_NONE, false, false, true>(
            A, B, nullptr, C, BATCH, HID, KHALF, KPAD, HID, bx, by, smem);
        return;
    }
    int aux = bid - MEGA_GEMM;
    if (aux < AUX_RED) { aux_popular_reduce(aux, part, out_pop); return; }
    aux -= AUX_RED;
    if (aux < AUX_W2) {
        aux_convert_pad(aux, enc_w2, W2c, (long)HID * EMB, (long)HID * EMB / 8);
        return;
    }
    aux -= AUX_W2;
    if (aux < AUX_WLR1) {
        aux_convert_cols(aux, lk_w1, Wlr, HID, 2 * HID, 0, EMB * HID / 8);
        return;
    }
    aux -= AUX_WLR1;
    if (aux < AUX_WLR2) {
        aux_convert_cols(aux, rc_w1, Wlr, HID, 2 * HID, HID, EMB * HID / 8);
        return;
    }
    aux -= AUX_WLR2;
    if (aux < AUX_BLR) { aux_concat2(aux, lk_b1, rc_b1, blr, HID); return; }
    aux -= AUX_BLR;
    if (aux < AUX_W4) {
        aux_convert_pad(aux, lk_w2, W4c, (long)HID * NITEMS,
                        (long)HID * NITEMS / 8);
        return;
    }
    aux -= AUX_W4;
    aux_convert_pad(aux, rc_w2, W6c, (long)HID * NITEMS,
                    (long)HID * NITEMS / 8);
}

// ---------------------------------------------------------------------------
// Merged prep: premask+popular partials (w/ per-block mask probe) + W1 convert
// ---------------------------------------------------------------------------
#define PREM_X 79                       // ceil(KPAD/256)
#define PREM_BLOCKS (PREM_X * 16)       // 1264
#define W1_BLOCKS ((KPAD * HID / 8) / 256)  // 10048
#define PREP_BLOCKS (PREM_BLOCKS + W1_BLOCKS)

__global__ void prep_kernel(const float* __restrict__ likes,
                            const void* __restrict__ mask,
                            __half* __restrict__ noisy,
                            float* __restrict__ part,
                            const float* __restrict__ enc_w1,
                            __half* __restrict__ W1c) {
    int bid = blockIdx.x;
    if (bid >= PREM_BLOCKS) {
        aux_convert_pad(bid - PREM_BLOCKS, enc_w1, W1c,
                        (long)NITEMS * HID, (long)KPAD * HID / 8);
        return;
    }
    const int mode = probe_mode_block((const unsigned int*)mask);
    const int col = (bid % PREM_X) * 256 + threadIdx.x;
    if (col >= KPAD) return;
    const int r0 = (bid / PREM_X) * 128;

    if (col >= NITEMS) {  // padding region: zero noisy, no popular
        const __half hz = __float2half_rn(0.f);
        for (int r = 0; r < 128; r++)
            noisy[(size_t)(r0 + r) * KPAD + col] = hz;
        return;
    }

    const unsigned char* m8 = (const unsigned char*)mask;
    const int*           mi = (const int*)mask;
    const float*         mf = (const float*)mask;

    float sum = 0.f;
    #pragma unroll 4
    for (int r = 0; r < 128; r++) {
        size_t e = (size_t)(r0 + r) * NITEMS + col;
        float v = likes[e];
        sum += v;
        bool drop;
        if (mode == 0)      drop = (m8[e] != 0);
        else if (mode == 1) drop = (mi[e] != 0);
        else                drop = (mf[e] != 0.f);
        noisy[(size_t)(r0 + r) * KPAD + col] = __float2half_rn(drop ? 0.f : v);
    }
    part[(bid / PREM_X) * NITEMS + col] = sum;
}

// combine split-K partials: Hh = fp16(relu(p0 + p1 + bias))
__global__ void combine_splitk_kernel(const float* __restrict__ p,
                                      const float* __restrict__ bias,
                                      __half* __restrict__ out) {
    const size_t MN = (size_t)BATCH * HID;
    size_t e = ((size_t)blockIdx.x * 256 + threadIdx.x) * 4;
    if (e >= MN) return;
    int col = (int)(e & (HID - 1));
    float4 a = *reinterpret_cast<const float4*>(p + e);
    float4 b = *reinterpret_cast<const float4*>(p + MN + e);
    float4 bb = *reinterpret_cast<const float4*>(bias + col);
    float x0 = fmaxf(a.x + b.x + bb.x, 0.f);
    float x1 = fmaxf(a.y + b.y + bb.y, 0.f);
    float x2 = fmaxf(a.z + b.z + bb.z, 0.f);
    float x3 = fmaxf(a.w + b.w + bb.w, 0.f);
    __half2* dst = reinterpret_cast<__half2*>(out + e);
    dst[0] = __floats2half2_rn(x0, x1);
    dst[1] = __floats2half2_rn(x2, x3);
}

// per-row l2 normalize; emit fp16 normalized AND fp16 copy of E
__global__ void norm_half_kernel(const float* __restrict__ E,
                                 __half* __restrict__ Nrmh,
                                 __half* __restrict__ Eh) {
    int row = blockIdx.x;
    int t = threadIdx.x;
    float4 v = reinterpret_cast<const float4*>(E + (size_t)row * EMB)[t];
    float ss = v.x * v.x + v.y * v.y + v.z * v.z + v.w * v.w;
    #pragma unroll
    for (int o = 16; o > 0; o >>= 1)
        ss += __shfl_xor_sync(0xFFFFFFFFu, ss, o);
    __shared__ float ws[4];
    if ((t & 31) == 0) ws[t >> 5] = ss;
    __syncthreads();
    float tot = ws[0] + ws[1] + ws[2] + ws[3];
    float inv = rsqrtf(fmaxf(tot, 1e-12f));
    __half2* eh = reinterpret_cast<__half2*>(Eh + (size_t)row * EMB + t * 4);
    eh[0] = __floats2half2_rn(v.x, v.y);
    eh[1] = __floats2half2_rn(v.z, v.w);
    __half2* nh = reinterpret_cast<__half2*>(Nrmh + (size_t)row * EMB + t * 4);
    nh[0] = __floats2half2_rn(v.x * inv, v.y * inv);
    nh[1] = __floats2half2_rn(v.z * inv, v.w * inv);
}

#define NO_DUAL nullptr, nullptr, nullptr, nullptr, 0x40000000

// ---------------------------------------------------------------------------
// Launch
// ---------------------------------------------------------------------------
extern "C" void kernel_launch(void* const* d_in, const int* in_sizes, int n_in,
                              void* d_out, int out_size) {
    const float* likes  = (const float*)d_in[1];
    const void*  nmask  = d_in[2];
    const float* enc_w1 = (const float*)d_in[3];
    const float* enc_b1 = (const float*)d_in[4];
    const float* enc_w2 = (const float*)d_in[5];
    const float* enc_b2 = (const float*)d_in[6];
    const float* lk_w1  = (const float*)d_in[7];
    const float* lk_b1  = (const float*)d_in[8];
    const float* lk_w2  = (const float*)d_in[9];
    const float* lk_b2  = (const float*)d_in[10];
    const float* rc_w1  = (const float*)d_in[11];
    const float* rc_b1  = (const float*)d_in[12];
    const float* rc_w2  = (const float*)d_in[13];
    const float* rc_b2  = (const float*)d_in[14];

    float* out       = (float*)d_out;
    float* out_likes = out;
    float* out_sim   = out_likes + (size_t)BATCH * NITEMS;
    float* out_rec   = out_sim + (size_t)BATCH * BATCH;
    float* out_pop   = out_rec + (size_t)BATCH * NITEMS;

    __half *noisyh, *W1c, *W2c, *Wlr, *W4c, *W6c, *Hh, *Hh2, *Eh, *Nrmh;
    float *E, *part, *blr, *psum;
    cudaGetSymbolAddress((void**)&noisyh, g_noisyh);
    cudaGetSymbolAddress((void**)&W1c, g_W1c);
    cudaGetSymbolAddress((void**)&W2c, g_W2c);
    cudaGetSymbolAddress((void**)&Wlr, g_Wlr);
    cudaGetSymbolAddress((void**)&W4c, g_W4c);
    cudaGetSymbolAddress((void**)&W6c, g_W6c);
    cudaGetSymbolAddress((void**)&blr, g_blr);
    cudaGetSymbolAddress((void**)&psum, g_psum);
    cudaGetSymbolAddress((void**)&Hh, g_Hh);
    cudaGetSymbolAddress((void**)&Hh2, g_Hh2);
    cudaGetSymbolAddress((void**)&E, g_E);
    cudaGetSymbolAddress((void**)&Eh, g_Eh);
    cudaGetSymbolAddress((void**)&Nrmh, g_Nrmh);
    cudaGetSymbolAddress((void**)&part, g_part);

    const int smem = NSTAGE * SSZ;      // 96KB (BN=128 body)
    const int smem64 = NSTAGE * SSZ64;  // 72KB (BN=64 body)
    cudaFuncSetAttribute(mega_kernel,
                         cudaFuncAttributeMaxDynamicSharedMemorySize, smem);
    cudaFuncSetAttribute(simhid_kernel,
                         cudaFuncAttributeMaxDynamicSharedMemorySize, smem);
    cudaFuncSetAttribute(gemm2_kernel,
                         cudaFuncAttributeMaxDynamicSharedMemorySize, smem64);
    cudaFuncSetAttribute(hmma_gemm<ACT_SIG, true, false, true>,
                         cudaFuncAttributeMaxDynamicSharedMemorySize, smem);

    // 1: merged prep -- denoise+popular partials (self-probing) + W1 convert
    prep_kernel<<<PREP_BLOCKS, 256>>>(likes, nmask, noisyh, part, enc_w1, W1c);
    // 2: MEGA -- split-K gemm1 + all remaining independent prep work
    mega_kernel<<<MEGA_BLOCKS, 256, smem>>>(
        noisyh, W1c, psum, part, out_pop,
        enc_w2, W2c, lk_w1, rc_w1, Wlr, lk_b1, rc_b1, blr,
        lk_w2, W4c, rc_w2, W6c);
    // 3: combine partials -> Hh = fp16(relu(p0+p1+b1))
    combine_splitk_kernel<<<(int)(((size_t)BATCH * HID / 4 + 255) / 256), 256>>>(
        psum, enc_b1, Hh);

    // 4: encoder layer 2 (128x64 tiles -> 128 CTAs)
    gemm2_kernel<<<dim3(BATCH / 128, EMB / 64), 256, smem64>>>(
        Hh, W2c, enc_b2, E);
    // 5: norm
    norm_half_kernel<<<BATCH, 128>>>(E, Nrmh, Eh);

    // 6: merged sim (upper triangle + mirror) + head-hidden (392 CTAs)
    simhid_kernel<<<392, 256, smem>>>(Nrmh, out_sim, Eh, Wlr, blr, Hh2);

    // 7: BOTH head outputs in ONE launch (wave merge)
    const int nTiles = (NITEMS + 127) / 128;  // 157
    hmma_gemm<ACT_SIG, true, false, true>
        <<<dim3(BATCH / 128, 2 * nTiles), 256, smem>>>(
        Hh2, W4c, lk_b2, out_likes, BATCH, NITEMS, HID, 2 * HID, NITEMS,
        Hh2 + HID, W6c, rc_b2, out_rec, nTiles);
}